// round 5
// baseline (speedup 1.0000x reference)
#include <cuda_runtime.h>
#include <cuda_bf16.h>
#include <cstdint>

#define N_NODES 100000
#define N_HE    30000
#define N_INC   300000
#define IN_CH   128
#define HID     256
#define OUT_CH  128
#define BN_EPS  1e-5f

// ---------------- device scratch (allocation-free) ----------------
__device__ float g_X1[(size_t)N_NODES * HID];   // GEMM out / AGG (fp32 staging)
__device__ float g_HE[(size_t)N_HE   * HID];    // hyperedge features
__device__ __nv_bfloat16 g_Xs[(size_t)N_NODES * 3 * HID]; // split activations [M, 3K]
__device__ __nv_bfloat16 g_Ws[(size_t)HID * 3 * HID];     // split weights [N, 3K] (transposed)

__device__ int g_nd_cnt[N_NODES];
__device__ int g_he_cnt[N_HE];
__device__ int g_nd_off[N_NODES + 1];
__device__ int g_he_off[N_HE + 1];
__device__ int g_nd_hes[N_INC];
__device__ int g_he_nodes[N_INC];

__device__ float g_sum[HID];
__device__ float g_sumsq[HID];

// ---------------- helpers ----------------
__device__ __forceinline__ uint32_t smem_to_u32(const void* p) {
    uint32_t a;
    asm("{ .reg .u64 t; cvta.to.shared.u64 t, %1; cvt.u32.u64 %0, t; }" : "=r"(a) : "l"(p));
    return a;
}
#define SWZ(off) ((off) ^ (((off) >> 3) & 0x70))

__device__ __forceinline__ void cp_async16(uint32_t dst, const void* src) {
    asm volatile("cp.async.cg.shared.global [%0], [%1], 16;" :: "r"(dst), "l"(src) : "memory");
}

// pack 2 floats' bf16-hi parts
__device__ __forceinline__ uint32_t pack_hi2(float x, float y) {
    __nv_bfloat162 h;
    h.x = __float2bfloat16(x);
    h.y = __float2bfloat16(y);
    return *reinterpret_cast<uint32_t*>(&h);
}
__device__ __forceinline__ uint32_t pack_lo2(float x, float y, uint32_t hi2) {
    __nv_bfloat162 h = *reinterpret_cast<__nv_bfloat162*>(&hi2);
    __nv_bfloat162 l;
    l.x = __float2bfloat16(x - __bfloat162float(h.x));
    l.y = __float2bfloat16(y - __bfloat162float(h.y));
    return *reinterpret_cast<uint32_t*>(&l);
}

// ---------------- CSR build ----------------
__global__ void k_hist(const int* __restrict__ node_idx, const int* __restrict__ he_idx) {
    int i = blockIdx.x * blockDim.x + threadIdx.x;
    if (i < N_INC) {
        atomicAdd(&g_nd_cnt[node_idx[i]], 1);
        atomicAdd(&g_he_cnt[he_idx[i]], 1);
    }
}

__global__ void k_scan(const int* __restrict__ cnt, int* __restrict__ off, int n) {
    __shared__ int warp_sums[32];
    __shared__ int s_carry;
    int tid = threadIdx.x, lane = tid & 31, wid = tid >> 5;
    if (tid == 0) s_carry = 0;
    __syncthreads();
    for (int base = 0; base < n; base += 1024) {
        int v = (base + tid < n) ? cnt[base + tid] : 0;
        int x = v;
#pragma unroll
        for (int o = 1; o < 32; o <<= 1) {
            int t = __shfl_up_sync(0xFFFFFFFFu, x, o);
            if (lane >= o) x += t;
        }
        if (lane == 31) warp_sums[wid] = x;
        __syncthreads();
        if (wid == 0) {
            int w = warp_sums[lane];
            int y = w;
#pragma unroll
            for (int o = 1; o < 32; o <<= 1) {
                int t = __shfl_up_sync(0xFFFFFFFFu, y, o);
                if (lane >= o) y += t;
            }
            warp_sums[lane] = y - w;
        }
        __syncthreads();
        int incl = x + warp_sums[wid];
        if (base + tid < n) off[base + tid] = s_carry + incl - v;
        __syncthreads();
        if (tid == 1023) s_carry += incl;
        __syncthreads();
    }
    if (threadIdx.x == 0) off[n] = s_carry;
}

__global__ void k_scatter(const int* __restrict__ node_idx, const int* __restrict__ he_idx) {
    int i = blockIdx.x * blockDim.x + threadIdx.x;
    if (i < N_INC) {
        int n = node_idx[i], e = he_idx[i];
        int p = atomicAdd(&g_he_cnt[e], 1);
        g_he_nodes[g_he_off[e] + p] = n;
        int q = atomicAdd(&g_nd_cnt[n], 1);
        g_nd_hes[g_nd_off[n] + q] = e;
    }
}

// ---------------- weight split ----------------
// W [K,N] fp32 -> Ws [N, 3K] bf16 (transposed), row layout [hi(K) | hi(K) | lo(K)]
__global__ void k_split_W(const float* __restrict__ W, __nv_bfloat16* __restrict__ Ws, int K, int N) {
    int i = blockIdx.x * blockDim.x + threadIdx.x;
    if (i >= K * N) return;
    int k = i / N, n = i - k * N;
    float v = W[i];
    __nv_bfloat16 h = __float2bfloat16(v);
    __nv_bfloat16 l = __float2bfloat16(v - __bfloat162float(h));
    __nv_bfloat16* O = Ws + (size_t)n * 3 * K;
    O[k] = h;
    O[K + k] = h;
    O[2 * K + k] = l;
}

// ---------------- HMMA bf16 GEMM: C[M,N] = A[M,Kt] @ B[N,Kt]^T ----------------
__global__ void __launch_bounds__(256, 2)
gemm_bf16_mma(const __nv_bfloat16* __restrict__ A, const __nv_bfloat16* __restrict__ B,
              float* __restrict__ C, int M, int Kt, int N,
              const float* __restrict__ bias, int do_relu)
{
    extern __shared__ char smc[];
    const uint32_t sbase = smem_to_u32(smc);
    const int tid  = threadIdx.x;
    const int lane = tid & 31;
    const int wid  = tid >> 5;
    const int wm   = wid >> 1;
    const int wn   = wid & 1;
    const int row0  = blockIdx.y * 128;
    const int nblk0 = blockIdx.x * 128;

    float acc[2][8][4];
#pragma unroll
    for (int i = 0; i < 2; i++)
#pragma unroll
        for (int j = 0; j < 8; j++)
#pragma unroll
            for (int k = 0; k < 4; k++) acc[i][j][k] = 0.f;

    uint32_t a_off[2], b_off[4];
#pragma unroll
    for (int mf = 0; mf < 2; mf++)
        a_off[mf] = (uint32_t)((wm * 32 + mf * 16 + (lane & 15)) * 128 + (lane >> 4) * 16);
#pragma unroll
    for (int nf4 = 0; nf4 < 4; nf4++)
        b_off[nf4] = (uint32_t)((wn * 64 + nf4 * 16 + (lane & 7) + ((lane >> 4) & 1) * 8) * 128
                                + ((lane >> 3) & 1) * 16);

    const int nch = Kt >> 6;

    auto load_chunk = [&](int c, int buf) {
        const __nv_bfloat16* Ag = A + (size_t)row0 * Kt + c * 64;
        const __nv_bfloat16* Bg = B + (size_t)nblk0 * Kt + c * 64;
        uint32_t ab = sbase + buf * 16384;
        uint32_t bb = sbase + 32768 + buf * 16384;
#pragma unroll
        for (int it = 0; it < 8; it++) {
            int i = tid + it * 256;
            if (i < 1024) {
                int r = i >> 3, q = i & 7;
                if (row0 + r < M)
                    cp_async16(ab + SWZ((uint32_t)(r * 128 + q * 16)),
                               Ag + (size_t)r * Kt + q * 8);
            } else {
                int j = i - 1024;
                int r = j >> 3, q = j & 7;
                cp_async16(bb + SWZ((uint32_t)(r * 128 + q * 16)),
                           Bg + (size_t)r * Kt + q * 8);
            }
        }
        asm volatile("cp.async.commit_group;" ::: "memory");
    };

    load_chunk(0, 0);

    for (int c = 0; c < nch; c++) {
        int buf = c & 1;
        if (c + 1 < nch) {
            load_chunk(c + 1, (c + 1) & 1);
            asm volatile("cp.async.wait_group 1;" ::: "memory");
        } else {
            asm volatile("cp.async.wait_group 0;" ::: "memory");
        }
        __syncthreads();

        uint32_t ab = sbase + buf * 16384;
        uint32_t bb = sbase + 32768 + buf * 16384;
#pragma unroll
        for (int k16 = 0; k16 < 4; k16++) {
            uint32_t a[2][4], b[4][4];
#pragma unroll
            for (int mf = 0; mf < 2; mf++) {
                uint32_t addr = ab + SWZ(a_off[mf] + (uint32_t)(k16 * 32));
                asm volatile("ldmatrix.sync.aligned.m8n8.x4.shared.b16 {%0,%1,%2,%3}, [%4];"
                             : "=r"(a[mf][0]), "=r"(a[mf][1]), "=r"(a[mf][2]), "=r"(a[mf][3])
                             : "r"(addr));
            }
#pragma unroll
            for (int nf4 = 0; nf4 < 4; nf4++) {
                uint32_t addr = bb + SWZ(b_off[nf4] + (uint32_t)(k16 * 32));
                asm volatile("ldmatrix.sync.aligned.m8n8.x4.shared.b16 {%0,%1,%2,%3}, [%4];"
                             : "=r"(b[nf4][0]), "=r"(b[nf4][1]), "=r"(b[nf4][2]), "=r"(b[nf4][3])
                             : "r"(addr));
            }
#pragma unroll
            for (int mf = 0; mf < 2; mf++)
#pragma unroll
                for (int nf = 0; nf < 8; nf++) {
                    asm volatile(
                        "mma.sync.aligned.m16n8k16.row.col.f32.bf16.bf16.f32 "
                        "{%0,%1,%2,%3}, {%4,%5,%6,%7}, {%8,%9}, {%0,%1,%2,%3};"
                        : "+f"(acc[mf][nf][0]), "+f"(acc[mf][nf][1]),
                          "+f"(acc[mf][nf][2]), "+f"(acc[mf][nf][3])
                        : "r"(a[mf][0]), "r"(a[mf][1]), "r"(a[mf][2]), "r"(a[mf][3]),
                          "r"(b[nf >> 1][(nf & 1) * 2]), "r"(b[nf >> 1][(nf & 1) * 2 + 1]));
                }
        }
        __syncthreads();
    }

#pragma unroll
    for (int mf = 0; mf < 2; mf++) {
        int r0g = row0 + wm * 32 + mf * 16 + (lane >> 2);
        int r1g = r0g + 8;
#pragma unroll
        for (int nf = 0; nf < 8; nf++) {
            int col = nblk0 + wn * 64 + nf * 8 + (lane & 3) * 2;
            float2 v0 = make_float2(acc[mf][nf][0], acc[mf][nf][1]);
            float2 v1 = make_float2(acc[mf][nf][2], acc[mf][nf][3]);
            if (bias) {
                float bx = bias[col], by = bias[col + 1];
                v0.x += bx; v0.y += by;
                v1.x += bx; v1.y += by;
            }
            if (do_relu) {
                v0.x = fmaxf(v0.x, 0.f); v0.y = fmaxf(v0.y, 0.f);
                v1.x = fmaxf(v1.x, 0.f); v1.y = fmaxf(v1.y, 0.f);
            }
            if (r0g < M) *reinterpret_cast<float2*>(C + (size_t)r0g * N + col) = v0;
            if (r1g < M) *reinterpret_cast<float2*>(C + (size_t)r1g * N + col) = v1;
        }
    }
}

// ---------------- aggregation ----------------
__global__ void k_he_gather(const float* __restrict__ X, float* __restrict__ HE, int F4) {
    int e = blockIdx.x;
    int f = threadIdx.x;
    int s = g_he_off[e], t = g_he_off[e + 1];
    float4 acc = make_float4(0.f, 0.f, 0.f, 0.f);
    for (int j = s; j < t; j++) {
        int n = g_he_nodes[j];
        float4 v = reinterpret_cast<const float4*>(X)[(size_t)n * F4 + f];
        acc.x += v.x; acc.y += v.y; acc.z += v.z; acc.w += v.w;
    }
    float inv = (t > s) ? 1.0f / (float)(t - s) : 0.f;
    acc.x *= inv; acc.y *= inv; acc.z *= inv; acc.w *= inv;
    reinterpret_cast<float4*>(HE)[(size_t)e * F4 + f] = acc;
}

// node aggregation -> fp32 (bias!=null applies bias+relu)
__global__ void k_node_gather(const float* __restrict__ HE, const float* __restrict__ bias,
                              float* __restrict__ OUT, int F4) {
    int n = blockIdx.x;
    int f = threadIdx.x;
    int s = g_nd_off[n], t = g_nd_off[n + 1];
    float4 acc = make_float4(0.f, 0.f, 0.f, 0.f);
    for (int j = s; j < t; j++) {
        int e = g_nd_hes[j];
        float4 v = reinterpret_cast<const float4*>(HE)[(size_t)e * F4 + f];
        acc.x += v.x; acc.y += v.y; acc.z += v.z; acc.w += v.w;
    }
    float inv = (t > s) ? 1.0f / (float)(t - s) : 0.f;
    if (bias) {
        float4 b4 = reinterpret_cast<const float4*>(bias)[f];
        acc.x = fmaxf(fmaf(acc.x, inv, b4.x), 0.f);
        acc.y = fmaxf(fmaf(acc.y, inv, b4.y), 0.f);
        acc.z = fmaxf(fmaf(acc.z, inv, b4.z), 0.f);
        acc.w = fmaxf(fmaf(acc.w, inv, b4.w), 0.f);
    } else {
        acc.x *= inv; acc.y *= inv; acc.z *= inv; acc.w *= inv;
    }
    reinterpret_cast<float4*>(OUT)[(size_t)n * F4 + f] = acc;
}

// node aggregation -> split bf16 [hi(F)|lo(F)|hi(F)] directly (layer 1, F=128, no bias)
__global__ void k_node_gather_split(const float* __restrict__ HE,
                                    __nv_bfloat16* __restrict__ Xs, int F) {
    int n = blockIdx.x;
    int f = threadIdx.x;               // F/4 threads
    int F4 = F >> 2;
    int s = g_nd_off[n], t = g_nd_off[n + 1];
    float4 acc = make_float4(0.f, 0.f, 0.f, 0.f);
    for (int j = s; j < t; j++) {
        int e = g_nd_hes[j];
        float4 v = reinterpret_cast<const float4*>(HE)[(size_t)e * F4 + f];
        acc.x += v.x; acc.y += v.y; acc.z += v.z; acc.w += v.w;
    }
    float inv = (t > s) ? 1.0f / (float)(t - s) : 0.f;
    acc.x *= inv; acc.y *= inv; acc.z *= inv; acc.w *= inv;

    uint32_t h0 = pack_hi2(acc.x, acc.y);
    uint32_t h1 = pack_hi2(acc.z, acc.w);
    uint32_t l0 = pack_lo2(acc.x, acc.y, h0);
    uint32_t l1 = pack_lo2(acc.z, acc.w, h1);
    __nv_bfloat16* row = Xs + (size_t)n * 3 * F;
    int c = f * 4;
    *reinterpret_cast<uint2*>(row + c)          = make_uint2(h0, h1);
    *reinterpret_cast<uint2*>(row + F + c)      = make_uint2(l0, l1);
    *reinterpret_cast<uint2*>(row + 2 * F + c)  = make_uint2(h0, h1);
}

// ---------------- batch norm ----------------
#define BN_ROWS_PER_BLOCK 100
__global__ void k_bn_stats(const float* __restrict__ X) {
    int f = threadIdx.x;
    int r0 = blockIdx.x * BN_ROWS_PER_BLOCK;
    float s = 0.f, ss = 0.f;
    for (int r = 0; r < BN_ROWS_PER_BLOCK; r++) {
        int row = r0 + r;
        if (row >= N_NODES) break;
        float v = X[(size_t)row * HID + f];
        s += v;
        ss += v * v;
    }
    atomicAdd(&g_sum[f], s);
    atomicAdd(&g_sumsq[f], ss);
}

// BN apply + 3-term split fused: X1 fp32 [N,256] -> Xs bf16 [N, 768]
__global__ void k_bn_apply_split(const float* __restrict__ X, __nv_bfloat16* __restrict__ Xs,
                                 const float* __restrict__ g, const float* __restrict__ be) {
    int idx = blockIdx.x * blockDim.x + threadIdx.x;   // over N*64
    if (idx >= N_NODES * (HID / 4)) return;
    int f4 = idx & (HID / 4 - 1);
    int row = idx >> 6;                // idx / 64
    float4 sm = reinterpret_cast<const float4*>(g_sum)[f4];
    float4 sq = reinterpret_cast<const float4*>(g_sumsq)[f4];
    float4 gg = reinterpret_cast<const float4*>(g)[f4];
    float4 bb = reinterpret_cast<const float4*>(be)[f4];
    const float invN = 1.0f / (float)N_NODES;
    float4 x = reinterpret_cast<const float4*>(X)[idx];
    float4 y;
    { float m = sm.x * invN; float v = sq.x * invN - m * m;
      float sc = gg.x * rsqrtf(v + BN_EPS); y.x = (x.x - m) * sc + bb.x; }
    { float m = sm.y * invN; float v = sq.y * invN - m * m;
      float sc = gg.y * rsqrtf(v + BN_EPS); y.y = (x.y - m) * sc + bb.y; }
    { float m = sm.z * invN; float v = sq.z * invN - m * m;
      float sc = gg.z * rsqrtf(v + BN_EPS); y.z = (x.z - m) * sc + bb.z; }
    { float m = sm.w * invN; float v = sq.w * invN - m * m;
      float sc = gg.w * rsqrtf(v + BN_EPS); y.w = (x.w - m) * sc + bb.w; }

    uint32_t h0 = pack_hi2(y.x, y.y);
    uint32_t h1 = pack_hi2(y.z, y.w);
    uint32_t l0 = pack_lo2(y.x, y.y, h0);
    uint32_t l1 = pack_lo2(y.z, y.w, h1);
    __nv_bfloat16* orow = Xs + (size_t)row * (3 * HID);
    int c = f4 * 4;
    *reinterpret_cast<uint2*>(orow + c)            = make_uint2(h0, h1);
    *reinterpret_cast<uint2*>(orow + HID + c)      = make_uint2(l0, l1);
    *reinterpret_cast<uint2*>(orow + 2 * HID + c)  = make_uint2(h0, h1);
}

// ---------------- launch ----------------
extern "C" void kernel_launch(void* const* d_in, const int* in_sizes, int n_in,
                              void* d_out, int out_size) {
    const float* x    = (const float*)d_in[0];
    const int*   edge = (const int*)d_in[1];
    const int*   node_idx = edge;
    const int*   he_idx   = edge + N_INC;
    const float* W1 = (const float*)d_in[2];
    const float* b1 = (const float*)d_in[3];
    const float* g1 = (const float*)d_in[4];
    const float* be1 = (const float*)d_in[5];
    const float* W2 = (const float*)d_in[6];
    const float* b2 = (const float*)d_in[7];
    const float* g2 = (const float*)d_in[8];
    const float* be2 = (const float*)d_in[9];
    const float* W3 = (const float*)d_in[10];
    const float* b3 = (const float*)d_in[11];
    float* out = (float*)d_out;

    void *p_X1, *p_HE, *p_Xs, *p_Ws, *p_nd_cnt, *p_he_cnt, *p_sum, *p_sumsq;
    cudaGetSymbolAddress(&p_X1, g_X1);
    cudaGetSymbolAddress(&p_HE, g_HE);
    cudaGetSymbolAddress(&p_Xs, g_Xs);
    cudaGetSymbolAddress(&p_Ws, g_Ws);
    cudaGetSymbolAddress(&p_nd_cnt, g_nd_cnt);
    cudaGetSymbolAddress(&p_he_cnt, g_he_cnt);
    cudaGetSymbolAddress(&p_sum, g_sum);
    cudaGetSymbolAddress(&p_sumsq, g_sumsq);
    float* X1 = (float*)p_X1;
    float* HE = (float*)p_HE;
    __nv_bfloat16* Xs = (__nv_bfloat16*)p_Xs;
    __nv_bfloat16* Ws = (__nv_bfloat16*)p_Ws;

    void *p_nd_off, *p_he_off;
    cudaGetSymbolAddress(&p_nd_off, g_nd_off);
    cudaGetSymbolAddress(&p_he_off, g_he_off);

    const int GEMM_SMEM = 65536;
    cudaFuncSetAttribute(gemm_bf16_mma, cudaFuncAttributeMaxDynamicSharedMemorySize, GEMM_SMEM);
    const int mtiles = (N_NODES + 127) / 128;   // 782

    // ---- CSR build ----
    cudaMemsetAsync(p_nd_cnt, 0, N_NODES * sizeof(int));
    cudaMemsetAsync(p_he_cnt, 0, N_HE * sizeof(int));
    k_hist<<<(N_INC + 255) / 256, 256>>>(node_idx, he_idx);
    k_scan<<<1, 1024>>>((const int*)p_nd_cnt, (int*)p_nd_off, N_NODES);
    k_scan<<<1, 1024>>>((const int*)p_he_cnt, (int*)p_he_off, N_HE);
    cudaMemsetAsync(p_nd_cnt, 0, N_NODES * sizeof(int));
    cudaMemsetAsync(p_he_cnt, 0, N_HE * sizeof(int));
    k_scatter<<<(N_INC + 255) / 256, 256>>>(node_idx, he_idx);

    const int bn_grid = (N_NODES + BN_ROWS_PER_BLOCK - 1) / BN_ROWS_PER_BLOCK;
    const int apply_grid = (N_NODES * (HID / 4) + 255) / 256;

    // ---- layer 1: aggregate FIRST at 128 ch, split fused into gather ----
    {
        k_he_gather<<<N_HE, IN_CH / 4>>>(x, HE, IN_CH / 4);
        k_node_gather_split<<<N_NODES, IN_CH / 4>>>(HE, Xs, IN_CH);  // -> Xs [M,384]
        k_split_W<<<(IN_CH * HID + 255) / 256, 256>>>(W1, Ws, IN_CH, HID);
        dim3 grid(HID / 128, mtiles);
        gemm_bf16_mma<<<grid, 256, GEMM_SMEM>>>(Xs, Ws, X1, N_NODES, 3 * IN_CH, HID, b1, 1);
        cudaMemsetAsync(p_sum, 0, HID * sizeof(float));
        cudaMemsetAsync(p_sumsq, 0, HID * sizeof(float));
        k_bn_stats<<<bn_grid, HID>>>(X1);
        k_bn_apply_split<<<apply_grid, 256>>>(X1, Xs, g1, be1);      // -> Xs [M,768]
    }
    // ---- layer 2 ----
    {
        k_split_W<<<(HID * HID + 255) / 256, 256>>>(W2, Ws, HID, HID);
        dim3 grid(HID / 128, mtiles);
        gemm_bf16_mma<<<grid, 256, GEMM_SMEM>>>(Xs, Ws, X1, N_NODES, 3 * HID, HID, nullptr, 0);
        k_he_gather<<<N_HE, HID / 4>>>(X1, HE, HID / 4);
        k_node_gather<<<N_NODES, HID / 4>>>(HE, b2, X1, HID / 4);
        cudaMemsetAsync(p_sum, 0, HID * sizeof(float));
        cudaMemsetAsync(p_sumsq, 0, HID * sizeof(float));
        k_bn_stats<<<bn_grid, HID>>>(X1);
        k_bn_apply_split<<<apply_grid, 256>>>(X1, Xs, g2, be2);      // -> Xs [M,768]
    }
    // ---- layer 3 ----
    {
        k_split_W<<<(HID * OUT_CH + 255) / 256, 256>>>(W3, Ws, HID, OUT_CH);
        dim3 grid(OUT_CH / 128, mtiles);
        gemm_bf16_mma<<<grid, 256, GEMM_SMEM>>>(Xs, Ws, X1, N_NODES, 3 * HID, OUT_CH, nullptr, 0);
        k_he_gather<<<N_HE, OUT_CH / 4>>>(X1, HE, OUT_CH / 4);
        k_node_gather<<<N_NODES, OUT_CH / 4>>>(HE, b3, out, OUT_CH / 4);
    }
}

// round 6
// speedup vs baseline: 1.1480x; 1.1480x over previous
#include <cuda_runtime.h>
#include <cuda_bf16.h>
#include <cstdint>

#define N_NODES 100000
#define N_HE    30000
#define N_INC   300000
#define IN_CH   128
#define HID     256
#define OUT_CH  128
#define BN_EPS  1e-5f

// ---------------- device scratch (allocation-free) ----------------
__device__ float g_X1[(size_t)N_NODES * HID];   // GEMM out / AGG (fp32 staging)
__device__ float g_HE[(size_t)N_HE   * HID];    // hyperedge features
__device__ __nv_bfloat16 g_Xs[(size_t)N_NODES * 2 * HID];   // split activations [M, 2K] = [hi|lo]
__device__ __nv_bfloat16 g_W1s[(size_t)HID * 3 * IN_CH];    // [256, 384]
__device__ __nv_bfloat16 g_W2s[(size_t)HID * 3 * HID];      // [256, 768]
__device__ __nv_bfloat16 g_W3s[(size_t)OUT_CH * 3 * HID];   // [128, 768]

__device__ int g_nd_cnt[N_NODES];
__device__ int g_he_cnt[N_HE];
__device__ int g_nd_off[N_NODES + 1];
__device__ int g_he_off[N_HE + 1];
__device__ int g_nd_hes[N_INC];
__device__ int g_he_nodes[N_INC];

__device__ float g_sum[HID];
__device__ float g_sumsq[HID];

// ---------------- helpers ----------------
__device__ __forceinline__ uint32_t smem_to_u32(const void* p) {
    uint32_t a;
    asm("{ .reg .u64 t; cvta.to.shared.u64 t, %1; cvt.u32.u64 %0, t; }" : "=r"(a) : "l"(p));
    return a;
}
#define SWZ(off) ((off) ^ (((off) >> 3) & 0x70))

__device__ __forceinline__ void cp_async16(uint32_t dst, const void* src) {
    asm volatile("cp.async.cg.shared.global [%0], [%1], 16;" :: "r"(dst), "l"(src) : "memory");
}

__device__ __forceinline__ uint32_t pack_hi2(float x, float y) {
    __nv_bfloat162 h;
    h.x = __float2bfloat16(x);
    h.y = __float2bfloat16(y);
    return *reinterpret_cast<uint32_t*>(&h);
}
__device__ __forceinline__ uint32_t pack_lo2(float x, float y, uint32_t hi2) {
    __nv_bfloat162 h = *reinterpret_cast<__nv_bfloat162*>(&hi2);
    __nv_bfloat162 l;
    l.x = __float2bfloat16(x - __bfloat162float(h.x));
    l.y = __float2bfloat16(y - __bfloat162float(h.y));
    return *reinterpret_cast<uint32_t*>(&l);
}

// ---------------- CSR build ----------------
__global__ void k_hist(const int* __restrict__ node_idx, const int* __restrict__ he_idx) {
    int i = blockIdx.x * blockDim.x + threadIdx.x;
    if (i < N_INC) {
        atomicAdd(&g_nd_cnt[node_idx[i]], 1);
        atomicAdd(&g_he_cnt[he_idx[i]], 1);
    }
}

__global__ void k_scan(const int* __restrict__ cnt, int* __restrict__ off, int n) {
    __shared__ int warp_sums[32];
    __shared__ int s_carry;
    int tid = threadIdx.x, lane = tid & 31, wid = tid >> 5;
    if (tid == 0) s_carry = 0;
    __syncthreads();
    for (int base = 0; base < n; base += 1024) {
        int v = (base + tid < n) ? cnt[base + tid] : 0;
        int x = v;
#pragma unroll
        for (int o = 1; o < 32; o <<= 1) {
            int t = __shfl_up_sync(0xFFFFFFFFu, x, o);
            if (lane >= o) x += t;
        }
        if (lane == 31) warp_sums[wid] = x;
        __syncthreads();
        if (wid == 0) {
            int w = warp_sums[lane];
            int y = w;
#pragma unroll
            for (int o = 1; o < 32; o <<= 1) {
                int t = __shfl_up_sync(0xFFFFFFFFu, y, o);
                if (lane >= o) y += t;
            }
            warp_sums[lane] = y - w;
        }
        __syncthreads();
        int incl = x + warp_sums[wid];
        if (base + tid < n) off[base + tid] = s_carry + incl - v;
        __syncthreads();
        if (tid == 1023) s_carry += incl;
        __syncthreads();
    }
    if (threadIdx.x == 0) off[n] = s_carry;
}

__global__ void k_scatter(const int* __restrict__ node_idx, const int* __restrict__ he_idx) {
    int i = blockIdx.x * blockDim.x + threadIdx.x;
    if (i < N_INC) {
        int n = node_idx[i], e = he_idx[i];
        int p = atomicAdd(&g_he_cnt[e], 1);
        g_he_nodes[g_he_off[e] + p] = n;
        int q = atomicAdd(&g_nd_cnt[n], 1);
        g_nd_hes[g_nd_off[n] + q] = e;
    }
}

// ---------------- weight split ----------------
// W [K,N] fp32 -> Ws [N, 3K] bf16 (transposed), row layout [hi(K) | hi(K) | lo(K)]
__global__ void k_split_W(const float* __restrict__ W, __nv_bfloat16* __restrict__ Ws, int K, int N) {
    int i = blockIdx.x * blockDim.x + threadIdx.x;
    if (i >= K * N) return;
    int k = i / N, n = i - k * N;
    float v = W[i];
    __nv_bfloat16 h = __float2bfloat16(v);
    __nv_bfloat16 l = __float2bfloat16(v - __bfloat162float(h));
    __nv_bfloat16* O = Ws + (size_t)n * 3 * K;
    O[k] = h;
    O[K + k] = h;
    O[2 * K + k] = l;
}

// ---------------- HMMA bf16 GEMM ----------------
// C[M,N] = A'[M,3K] @ B[N,3K]^T where A' logical segments [hi|lo|hi] come from
// physical A stored [hi(K)|lo(K)] (stride 2K); B stored [hi|hi|lo] (stride 3K).
// CTA tile 128 x N (whole N), warps = 4(M) x N/64, warp tile 32x64.
// K-chunks of 64 double-buffered via cp.async, SW128 swizzle, ldmatrix+mma.sync.
__global__ void __launch_bounds__(512, 1)
gemm_bf16_mma(const __nv_bfloat16* __restrict__ A, const __nv_bfloat16* __restrict__ B,
              float* __restrict__ C, int M, int K, int N,
              const float* __restrict__ bias, int do_relu)
{
    extern __shared__ char smc[];
    const uint32_t sbase = smem_to_u32(smc);
    const int tid  = threadIdx.x;
    const int lane = tid & 31;
    const int wid  = tid >> 5;
    const int nwn  = N >> 6;              // N-slices of 64
    const int wm   = wid / nwn;           // 0..3
    const int wn   = wid % nwn;           // 0..nwn-1
    const int row0 = blockIdx.y * 128;
    const int nthreads = nwn * 4 * 32;    // 256 (N=128) or 512 (N=256)

    const int Astride = 2 * K;
    const int Bstride = 3 * K;
    const int nch = (3 * K) >> 6;
    const int kch2 = (2 * K) >> 6;        // boundary where A re-reads hi

    const uint32_t NB = (uint32_t)N * 128;

    float acc[2][8][4];
#pragma unroll
    for (int i = 0; i < 2; i++)
#pragma unroll
        for (int j = 0; j < 8; j++)
#pragma unroll
            for (int k = 0; k < 4; k++) acc[i][j][k] = 0.f;

    uint32_t a_off[2], b_off[4];
#pragma unroll
    for (int mf = 0; mf < 2; mf++)
        a_off[mf] = (uint32_t)((wm * 32 + mf * 16 + (lane & 15)) * 128 + (lane >> 4) * 16);
#pragma unroll
    for (int nf4 = 0; nf4 < 4; nf4++)
        b_off[nf4] = (uint32_t)((wn * 64 + nf4 * 16 + (lane & 7) + ((lane >> 4) & 1) * 8) * 128
                                + ((lane >> 3) & 1) * 16);

    const int a_items = 1024;             // 128 rows x 8 16B items
    const int total = a_items + N * 8;

    auto load_chunk = [&](int c, int buf) {
        int ac = (c < kch2) ? c : c - kch2;
        const __nv_bfloat16* Ag = A + (size_t)row0 * Astride + ac * 64;
        const __nv_bfloat16* Bg = B + c * 64;
        uint32_t ab = sbase + buf * 16384;
        uint32_t bb = sbase + 32768 + buf * NB;
        for (int i = tid; i < total; i += nthreads) {
            if (i < a_items) {
                int r = i >> 3, q = i & 7;
                if (row0 + r < M)
                    cp_async16(ab + SWZ((uint32_t)(r * 128 + q * 16)),
                               Ag + (size_t)r * Astride + q * 8);
            } else {
                int j = i - a_items;
                int r = j >> 3, q = j & 7;
                cp_async16(bb + SWZ((uint32_t)(r * 128 + q * 16)),
                           Bg + (size_t)r * Bstride + q * 8);
            }
        }
        asm volatile("cp.async.commit_group;" ::: "memory");
    };

    load_chunk(0, 0);

    for (int c = 0; c < nch; c++) {
        int buf = c & 1;
        if (c + 1 < nch) {
            load_chunk(c + 1, (c + 1) & 1);
            asm volatile("cp.async.wait_group 1;" ::: "memory");
        } else {
            asm volatile("cp.async.wait_group 0;" ::: "memory");
        }
        __syncthreads();

        uint32_t ab = sbase + buf * 16384;
        uint32_t bb = sbase + 32768 + buf * NB;
#pragma unroll
        for (int k16 = 0; k16 < 4; k16++) {
            uint32_t a[2][4], b[4][4];
#pragma unroll
            for (int mf = 0; mf < 2; mf++) {
                uint32_t addr = ab + SWZ(a_off[mf] + (uint32_t)(k16 * 32));
                asm volatile("ldmatrix.sync.aligned.m8n8.x4.shared.b16 {%0,%1,%2,%3}, [%4];"
                             : "=r"(a[mf][0]), "=r"(a[mf][1]), "=r"(a[mf][2]), "=r"(a[mf][3])
                             : "r"(addr));
            }
#pragma unroll
            for (int nf4 = 0; nf4 < 4; nf4++) {
                uint32_t addr = bb + SWZ(b_off[nf4] + (uint32_t)(k16 * 32));
                asm volatile("ldmatrix.sync.aligned.m8n8.x4.shared.b16 {%0,%1,%2,%3}, [%4];"
                             : "=r"(b[nf4][0]), "=r"(b[nf4][1]), "=r"(b[nf4][2]), "=r"(b[nf4][3])
                             : "r"(addr));
            }
#pragma unroll
            for (int mf = 0; mf < 2; mf++)
#pragma unroll
                for (int nf = 0; nf < 8; nf++) {
                    asm volatile(
                        "mma.sync.aligned.m16n8k16.row.col.f32.bf16.bf16.f32 "
                        "{%0,%1,%2,%3}, {%4,%5,%6,%7}, {%8,%9}, {%0,%1,%2,%3};"
                        : "+f"(acc[mf][nf][0]), "+f"(acc[mf][nf][1]),
                          "+f"(acc[mf][nf][2]), "+f"(acc[mf][nf][3])
                        : "r"(a[mf][0]), "r"(a[mf][1]), "r"(a[mf][2]), "r"(a[mf][3]),
                          "r"(b[nf >> 1][(nf & 1) * 2]), "r"(b[nf >> 1][(nf & 1) * 2 + 1]));
                }
        }
        __syncthreads();
    }

#pragma unroll
    for (int mf = 0; mf < 2; mf++) {
        int r0g = row0 + wm * 32 + mf * 16 + (lane >> 2);
        int r1g = r0g + 8;
#pragma unroll
        for (int nf = 0; nf < 8; nf++) {
            int col = wn * 64 + nf * 8 + (lane & 3) * 2;
            float2 v0 = make_float2(acc[mf][nf][0], acc[mf][nf][1]);
            float2 v1 = make_float2(acc[mf][nf][2], acc[mf][nf][3]);
            if (bias) {
                float bx = bias[col], by = bias[col + 1];
                v0.x += bx; v0.y += by;
                v1.x += bx; v1.y += by;
            }
            if (do_relu) {
                v0.x = fmaxf(v0.x, 0.f); v0.y = fmaxf(v0.y, 0.f);
                v1.x = fmaxf(v1.x, 0.f); v1.y = fmaxf(v1.y, 0.f);
            }
            if (r0g < M) *reinterpret_cast<float2*>(C + (size_t)r0g * N + col) = v0;
            if (r1g < M) *reinterpret_cast<float2*>(C + (size_t)r1g * N + col) = v1;
        }
    }
}

// ---------------- aggregation ----------------
__global__ void k_he_gather(const float* __restrict__ X, float* __restrict__ HE, int F4) {
    int e = blockIdx.x;
    int f = threadIdx.x;
    int s = g_he_off[e], t = g_he_off[e + 1];
    float4 acc = make_float4(0.f, 0.f, 0.f, 0.f);
    for (int j = s; j < t; j++) {
        int n = g_he_nodes[j];
        float4 v = reinterpret_cast<const float4*>(X)[(size_t)n * F4 + f];
        acc.x += v.x; acc.y += v.y; acc.z += v.z; acc.w += v.w;
    }
    float inv = (t > s) ? 1.0f / (float)(t - s) : 0.f;
    acc.x *= inv; acc.y *= inv; acc.z *= inv; acc.w *= inv;
    reinterpret_cast<float4*>(HE)[(size_t)e * F4 + f] = acc;
}

// node aggregation -> fp32 (bias!=null applies bias+relu)
__global__ void k_node_gather(const float* __restrict__ HE, const float* __restrict__ bias,
                              float* __restrict__ OUT, int F4) {
    int n = blockIdx.x;
    int f = threadIdx.x;
    int s = g_nd_off[n], t = g_nd_off[n + 1];
    float4 acc = make_float4(0.f, 0.f, 0.f, 0.f);
    for (int j = s; j < t; j++) {
        int e = g_nd_hes[j];
        float4 v = reinterpret_cast<const float4*>(HE)[(size_t)e * F4 + f];
        acc.x += v.x; acc.y += v.y; acc.z += v.z; acc.w += v.w;
    }
    float inv = (t > s) ? 1.0f / (float)(t - s) : 0.f;
    if (bias) {
        float4 b4 = reinterpret_cast<const float4*>(bias)[f];
        acc.x = fmaxf(fmaf(acc.x, inv, b4.x), 0.f);
        acc.y = fmaxf(fmaf(acc.y, inv, b4.y), 0.f);
        acc.z = fmaxf(fmaf(acc.z, inv, b4.z), 0.f);
        acc.w = fmaxf(fmaf(acc.w, inv, b4.w), 0.f);
    } else {
        acc.x *= inv; acc.y *= inv; acc.z *= inv; acc.w *= inv;
    }
    reinterpret_cast<float4*>(OUT)[(size_t)n * F4 + f] = acc;
}

// node aggregation -> split bf16 [hi(F)|lo(F)] directly (layer 1, no bias)
__global__ void k_node_gather_split(const float* __restrict__ HE,
                                    __nv_bfloat16* __restrict__ Xs, int F) {
    int n = blockIdx.x;
    int f = threadIdx.x;               // F/4 threads
    int F4 = F >> 2;
    int s = g_nd_off[n], t = g_nd_off[n + 1];
    float4 acc = make_float4(0.f, 0.f, 0.f, 0.f);
    for (int j = s; j < t; j++) {
        int e = g_nd_hes[j];
        float4 v = reinterpret_cast<const float4*>(HE)[(size_t)e * F4 + f];
        acc.x += v.x; acc.y += v.y; acc.z += v.z; acc.w += v.w;
    }
    float inv = (t > s) ? 1.0f / (float)(t - s) : 0.f;
    acc.x *= inv; acc.y *= inv; acc.z *= inv; acc.w *= inv;

    uint32_t h0 = pack_hi2(acc.x, acc.y);
    uint32_t h1 = pack_hi2(acc.z, acc.w);
    uint32_t l0 = pack_lo2(acc.x, acc.y, h0);
    uint32_t l1 = pack_lo2(acc.z, acc.w, h1);
    __nv_bfloat16* row = Xs + (size_t)n * 2 * F;
    int c = f * 4;
    *reinterpret_cast<uint2*>(row + c)     = make_uint2(h0, h1);
    *reinterpret_cast<uint2*>(row + F + c) = make_uint2(l0, l1);
}

// ---------------- batch norm ----------------
#define BN_ROWS_PER_BLOCK 250
__global__ void k_bn_stats(const float* __restrict__ X) {
    int f = threadIdx.x;
    int r0 = blockIdx.x * BN_ROWS_PER_BLOCK;
    float s = 0.f, ss = 0.f;
    for (int r = 0; r < BN_ROWS_PER_BLOCK; r++) {
        int row = r0 + r;
        if (row >= N_NODES) break;
        float v = X[(size_t)row * HID + f];
        s += v;
        ss += v * v;
    }
    atomicAdd(&g_sum[f], s);
    atomicAdd(&g_sumsq[f], ss);
}

// BN apply + 2-term split fused: X1 fp32 [N,256] -> Xs bf16 [N, 512] = [hi|lo]
__global__ void k_bn_apply_split(const float* __restrict__ X, __nv_bfloat16* __restrict__ Xs,
                                 const float* __restrict__ g, const float* __restrict__ be) {
    int idx = blockIdx.x * blockDim.x + threadIdx.x;   // over N*64
    if (idx >= N_NODES * (HID / 4)) return;
    int f4 = idx & (HID / 4 - 1);
    int row = idx >> 6;
    float4 sm = reinterpret_cast<const float4*>(g_sum)[f4];
    float4 sq = reinterpret_cast<const float4*>(g_sumsq)[f4];
    float4 gg = reinterpret_cast<const float4*>(g)[f4];
    float4 bb = reinterpret_cast<const float4*>(be)[f4];
    const float invN = 1.0f / (float)N_NODES;
    float4 x = reinterpret_cast<const float4*>(X)[idx];
    float4 y;
    { float m = sm.x * invN; float v = sq.x * invN - m * m;
      float sc = gg.x * rsqrtf(v + BN_EPS); y.x = (x.x - m) * sc + bb.x; }
    { float m = sm.y * invN; float v = sq.y * invN - m * m;
      float sc = gg.y * rsqrtf(v + BN_EPS); y.y = (x.y - m) * sc + bb.y; }
    { float m = sm.z * invN; float v = sq.z * invN - m * m;
      float sc = gg.z * rsqrtf(v + BN_EPS); y.z = (x.z - m) * sc + bb.z; }
    { float m = sm.w * invN; float v = sq.w * invN - m * m;
      float sc = gg.w * rsqrtf(v + BN_EPS); y.w = (x.w - m) * sc + bb.w; }

    uint32_t h0 = pack_hi2(y.x, y.y);
    uint32_t h1 = pack_hi2(y.z, y.w);
    uint32_t l0 = pack_lo2(y.x, y.y, h0);
    uint32_t l1 = pack_lo2(y.z, y.w, h1);
    __nv_bfloat16* orow = Xs + (size_t)row * (2 * HID);
    int c = f4 * 4;
    *reinterpret_cast<uint2*>(orow + c)       = make_uint2(h0, h1);
    *reinterpret_cast<uint2*>(orow + HID + c) = make_uint2(l0, l1);
}

// ---------------- launch ----------------
extern "C" void kernel_launch(void* const* d_in, const int* in_sizes, int n_in,
                              void* d_out, int out_size) {
    const float* x    = (const float*)d_in[0];
    const int*   edge = (const int*)d_in[1];
    const int*   node_idx = edge;
    const int*   he_idx   = edge + N_INC;
    const float* W1 = (const float*)d_in[2];
    const float* b1 = (const float*)d_in[3];
    const float* g1 = (const float*)d_in[4];
    const float* be1 = (const float*)d_in[5];
    const float* W2 = (const float*)d_in[6];
    const float* b2 = (const float*)d_in[7];
    const float* g2 = (const float*)d_in[8];
    const float* be2 = (const float*)d_in[9];
    const float* W3 = (const float*)d_in[10];
    const float* b3 = (const float*)d_in[11];
    float* out = (float*)d_out;

    void *p_X1, *p_HE, *p_Xs, *p_W1s, *p_W2s, *p_W3s;
    void *p_nd_cnt, *p_he_cnt, *p_sum, *p_sumsq, *p_nd_off, *p_he_off;
    cudaGetSymbolAddress(&p_X1, g_X1);
    cudaGetSymbolAddress(&p_HE, g_HE);
    cudaGetSymbolAddress(&p_Xs, g_Xs);
    cudaGetSymbolAddress(&p_W1s, g_W1s);
    cudaGetSymbolAddress(&p_W2s, g_W2s);
    cudaGetSymbolAddress(&p_W3s, g_W3s);
    cudaGetSymbolAddress(&p_nd_cnt, g_nd_cnt);
    cudaGetSymbolAddress(&p_he_cnt, g_he_cnt);
    cudaGetSymbolAddress(&p_sum, g_sum);
    cudaGetSymbolAddress(&p_sumsq, g_sumsq);
    cudaGetSymbolAddress(&p_nd_off, g_nd_off);
    cudaGetSymbolAddress(&p_he_off, g_he_off);
    float* X1 = (float*)p_X1;
    float* HE = (float*)p_HE;
    __nv_bfloat16* Xs  = (__nv_bfloat16*)p_Xs;
    __nv_bfloat16* W1s = (__nv_bfloat16*)p_W1s;
    __nv_bfloat16* W2s = (__nv_bfloat16*)p_W2s;
    __nv_bfloat16* W3s = (__nv_bfloat16*)p_W3s;

    const int GEMM_SMEM = 98304;   // 2x16KB A + 2x32KB B (N=256)
    cudaFuncSetAttribute(gemm_bf16_mma, cudaFuncAttributeMaxDynamicSharedMemorySize, GEMM_SMEM);
    const int mtiles = (N_NODES + 127) / 128;   // 782

    // ---- weight splits (independent, up front) ----
    k_split_W<<<(IN_CH * HID + 255) / 256, 256>>>(W1, W1s, IN_CH, HID);
    k_split_W<<<(HID * HID + 255) / 256, 256>>>(W2, W2s, HID, HID);
    k_split_W<<<(HID * OUT_CH + 255) / 256, 256>>>(W3, W3s, HID, OUT_CH);

    // ---- CSR build ----
    cudaMemsetAsync(p_nd_cnt, 0, N_NODES * sizeof(int));
    cudaMemsetAsync(p_he_cnt, 0, N_HE * sizeof(int));
    k_hist<<<(N_INC + 255) / 256, 256>>>(node_idx, he_idx);
    k_scan<<<1, 1024>>>((const int*)p_nd_cnt, (int*)p_nd_off, N_NODES);
    k_scan<<<1, 1024>>>((const int*)p_he_cnt, (int*)p_he_off, N_HE);
    cudaMemsetAsync(p_nd_cnt, 0, N_NODES * sizeof(int));
    cudaMemsetAsync(p_he_cnt, 0, N_HE * sizeof(int));
    k_scatter<<<(N_INC + 255) / 256, 256>>>(node_idx, he_idx);

    const int bn_grid = (N_NODES + BN_ROWS_PER_BLOCK - 1) / BN_ROWS_PER_BLOCK;
    const int apply_grid = (N_NODES * (HID / 4) + 255) / 256;

    // ---- layer 1: aggregate FIRST at 128 ch (A(xW)=(Ax)W), split fused into gather ----
    {
        k_he_gather<<<N_HE, IN_CH / 4>>>(x, HE, IN_CH / 4);
        k_node_gather_split<<<N_NODES, IN_CH / 4>>>(HE, Xs, IN_CH);   // -> Xs [M, 256]=[hi|lo]
        dim3 grid(1, mtiles);
        gemm_bf16_mma<<<grid, 512, GEMM_SMEM>>>(Xs, W1s, X1, N_NODES, IN_CH, HID, b1, 1);
        cudaMemsetAsync(p_sum, 0, HID * sizeof(float));
        cudaMemsetAsync(p_sumsq, 0, HID * sizeof(float));
        k_bn_stats<<<bn_grid, HID>>>(X1);
        k_bn_apply_split<<<apply_grid, 256>>>(X1, Xs, g1, be1);       // -> Xs [M, 512]
    }
    // ---- layer 2 ----
    {
        dim3 grid(1, mtiles);
        gemm_bf16_mma<<<grid, 512, GEMM_SMEM>>>(Xs, W2s, X1, N_NODES, HID, HID, nullptr, 0);
        k_he_gather<<<N_HE, HID / 4>>>(X1, HE, HID / 4);
        k_node_gather<<<N_NODES, HID / 4>>>(HE, b2, X1, HID / 4);
        cudaMemsetAsync(p_sum, 0, HID * sizeof(float));
        cudaMemsetAsync(p_sumsq, 0, HID * sizeof(float));
        k_bn_stats<<<bn_grid, HID>>>(X1);
        k_bn_apply_split<<<apply_grid, 256>>>(X1, Xs, g2, be2);       // -> Xs [M, 512]
    }
    // ---- layer 3 ----
    {
        dim3 grid(1, mtiles);
        gemm_bf16_mma<<<grid, 256, GEMM_SMEM>>>(Xs, W3s, X1, N_NODES, HID, OUT_CH, nullptr, 0);
        k_he_gather<<<N_HE, OUT_CH / 4>>>(X1, HE, OUT_CH / 4);
        k_node_gather<<<N_NODES, OUT_CH / 4>>>(HE, b3, out, OUT_CH / 4);
    }
}

// round 7
// speedup vs baseline: 1.4105x; 1.2287x over previous
#include <cuda_runtime.h>
#include <cuda_bf16.h>
#include <cuda_fp16.h>
#include <cstdint>

#define N_NODES 100000
#define N_HE    30000
#define N_INC   300000
#define IN_CH   128
#define HID     256
#define OUT_CH  128
#define BN_EPS  1e-5f

// ---------------- device scratch (allocation-free) ----------------
__device__ float g_X1[(size_t)N_NODES * HID];   // GEMM out / AGG (fp32 staging)
__device__ float g_HE[(size_t)N_HE   * HID];    // hyperedge features
__device__ __half g_Xs[(size_t)N_NODES * 2 * HID];   // split activations [M, 2K] = [hi|lo]
__device__ __half g_W1s[(size_t)HID * 2 * IN_CH];    // [256, 256]
__device__ __half g_W2s[(size_t)HID * 2 * HID];      // [256, 512]
__device__ __half g_W3s[(size_t)OUT_CH * 2 * HID];   // [128, 512]

__device__ int g_nd_cnt[N_NODES];
__device__ int g_he_cnt[N_HE];
__device__ int g_nd_off[N_NODES + 1];
__device__ int g_he_off[N_HE + 1];
__device__ int g_nd_hes[N_INC];
__device__ int g_he_nodes[N_INC];
__device__ int g_bsum[64];

__device__ float g_sum[HID];
__device__ float g_sumsq[HID];

// ---------------- helpers ----------------
__device__ __forceinline__ uint32_t smem_to_u32(const void* p) {
    uint32_t a;
    asm("{ .reg .u64 t; cvta.to.shared.u64 t, %1; cvt.u32.u64 %0, t; }" : "=r"(a) : "l"(p));
    return a;
}
#define SWZ(off) ((off) ^ (((off) >> 3) & 0x70))

__device__ __forceinline__ void cp_async16(uint32_t dst, const void* src) {
    asm volatile("cp.async.cg.shared.global [%0], [%1], 16;" :: "r"(dst), "l"(src) : "memory");
}

__device__ __forceinline__ uint32_t pack_hi2h(float x, float y) {
    __half2 h = __floats2half2_rn(x, y);
    return *reinterpret_cast<uint32_t*>(&h);
}
__device__ __forceinline__ uint32_t pack_lo2h(float x, float y, uint32_t hi2) {
    __half2 h = *reinterpret_cast<__half2*>(&hi2);
    __half2 l = __floats2half2_rn(x - __half2float(h.x), y - __half2float(h.y));
    return *reinterpret_cast<uint32_t*>(&l);
}

// ---------------- CSR build ----------------
__global__ void k_hist(const int* __restrict__ node_idx, const int* __restrict__ he_idx) {
    int i = blockIdx.x * blockDim.x + threadIdx.x;
    if (i < N_INC) {
        atomicAdd(&g_nd_cnt[node_idx[i]], 1);
        atomicAdd(&g_he_cnt[he_idx[i]], 1);
    }
}

// ---- multi-block exclusive scan: cnt[n] -> off[n+1] ----
// pass 1: per-block (2048 elems) sums
__global__ void k_blk_sum(const int* __restrict__ cnt, int* __restrict__ bsum, int n) {
    int tid = threadIdx.x;                 // 256
    int base = blockIdx.x * 2048;
    int s = 0;
#pragma unroll
    for (int i = 0; i < 8; i++) {
        int idx = base + i * 256 + tid;
        if (idx < n) s += cnt[idx];
    }
#pragma unroll
    for (int o = 16; o > 0; o >>= 1) s += __shfl_xor_sync(0xFFFFFFFFu, s, o);
    __shared__ int ws[8];
    if ((tid & 31) == 0) ws[tid >> 5] = s;
    __syncthreads();
    if (tid == 0) {
        int t = 0;
#pragma unroll
        for (int w = 0; w < 8; w++) t += ws[w];
        bsum[blockIdx.x] = t;
    }
}
// pass 2: single-block exclusive scan of block sums (nb <= 1024); writes off[n]=total
__global__ void k_bsum_scan(int* __restrict__ bsum, int* __restrict__ off, int nb, int n) {
    int tid = threadIdx.x;   // 1024
    int lane = tid & 31, w = tid >> 5;
    int v = (tid < nb) ? bsum[tid] : 0;
    int x = v;
#pragma unroll
    for (int o = 1; o < 32; o <<= 1) {
        int t = __shfl_up_sync(0xFFFFFFFFu, x, o);
        if (lane >= o) x += t;
    }
    __shared__ int ws[32];
    if (lane == 31) ws[w] = x;
    __syncthreads();
    if (w == 0) {
        int y = ws[lane];
        int z = y;
#pragma unroll
        for (int o = 1; o < 32; o <<= 1) {
            int t = __shfl_up_sync(0xFFFFFFFFu, z, o);
            if (lane >= o) z += t;
        }
        ws[lane] = z - y;
    }
    __syncthreads();
    int excl = x - v + ws[w];
    if (tid < nb) bsum[tid] = excl;
    if (tid == nb - 1) off[n] = excl + v;
}
// pass 3: per-block scan with base
__global__ void k_blk_scan(const int* __restrict__ cnt, const int* __restrict__ bsum,
                           int* __restrict__ off, int n) {
    int tid = threadIdx.x; // 256
    int base = blockIdx.x * 2048;
    int v[8];
    int s = 0;
#pragma unroll
    for (int i = 0; i < 8; i++) {
        int idx = base + tid * 8 + i;
        v[i] = (idx < n) ? cnt[idx] : 0;
        s += v[i];
    }
    int lane = tid & 31, w = tid >> 5;
    int x = s;
#pragma unroll
    for (int o = 1; o < 32; o <<= 1) {
        int t = __shfl_up_sync(0xFFFFFFFFu, x, o);
        if (lane >= o) x += t;
    }
    __shared__ int ws[8];
    __shared__ int wexcl[8];
    if (lane == 31) ws[w] = x;
    __syncthreads();
    if (tid < 8) {
        int t = 0;
        for (int j = 0; j < tid; j++) t += ws[j];
        wexcl[tid] = t;
    }
    __syncthreads();
    int run = bsum[blockIdx.x] + wexcl[w] + (x - s);
#pragma unroll
    for (int i = 0; i < 8; i++) {
        int idx = base + tid * 8 + i;
        if (idx < n) off[idx] = run;
        run += v[i];
    }
}

__global__ void k_scatter(const int* __restrict__ node_idx, const int* __restrict__ he_idx) {
    int i = blockIdx.x * blockDim.x + threadIdx.x;
    if (i < N_INC) {
        int n = node_idx[i], e = he_idx[i];
        int p = atomicAdd(&g_he_cnt[e], 1);
        g_he_nodes[g_he_off[e] + p] = n;
        int q = atomicAdd(&g_nd_cnt[n], 1);
        g_nd_hes[g_nd_off[n] + q] = e;
    }
}

// ---------------- weight split ----------------
// W [K,N] fp32 -> Ws [N, 2K] fp16 (transposed), row layout [hi(K) | lo(K)]
__global__ void k_split_W(const float* __restrict__ W, __half* __restrict__ Ws, int K, int N) {
    int i = blockIdx.x * blockDim.x + threadIdx.x;
    if (i >= K * N) return;
    int k = i / N, n = i - k * N;
    float v = W[i];
    __half h = __float2half_rn(v);
    __half l = __float2half_rn(v - __half2float(h));
    __half* O = Ws + (size_t)n * 2 * K;
    O[k] = h;
    O[K + k] = l;
}

// ---------------- HMMA fp16 GEMM: C[M,N] = A[M,Kt] @ B[N,Kt]^T ----------------
// A,B fp16 row-major (Kt = 2K split dim). CTA tile 128 x N (whole N),
// warps = 4(M) x N/64, warp tile 32x64. K-chunks of 64 double-buffered via
// cp.async, SW128 swizzle, ldmatrix + mma.sync f16.
__global__ void __launch_bounds__(512, 1)
gemm_f16_mma(const __half* __restrict__ A, const __half* __restrict__ B,
             float* __restrict__ C, int M, int Kt, int N,
             const float* __restrict__ bias, int do_relu)
{
    extern __shared__ char smc[];
    const uint32_t sbase = smem_to_u32(smc);
    const int tid  = threadIdx.x;
    const int lane = tid & 31;
    const int wid  = tid >> 5;
    const int nwn  = N >> 6;              // N-slices of 64
    const int wm   = wid / nwn;
    const int wn   = wid % nwn;
    const int row0 = blockIdx.y * 128;
    const int nthreads = nwn * 4 * 32;    // 256 (N=128) or 512 (N=256)

    const int nch = Kt >> 6;
    const uint32_t NB = (uint32_t)N * 128;

    float acc[2][8][4];
#pragma unroll
    for (int i = 0; i < 2; i++)
#pragma unroll
        for (int j = 0; j < 8; j++)
#pragma unroll
            for (int k = 0; k < 4; k++) acc[i][j][k] = 0.f;

    uint32_t a_off[2], b_off[4];
#pragma unroll
    for (int mf = 0; mf < 2; mf++)
        a_off[mf] = (uint32_t)((wm * 32 + mf * 16 + (lane & 15)) * 128 + (lane >> 4) * 16);
#pragma unroll
    for (int nf4 = 0; nf4 < 4; nf4++)
        b_off[nf4] = (uint32_t)((wn * 64 + nf4 * 16 + (lane & 7) + ((lane >> 4) & 1) * 8) * 128
                                + ((lane >> 3) & 1) * 16);

    const int a_items = 1024;             // 128 rows x 8 16B items
    const int total = a_items + N * 8;

    auto load_chunk = [&](int c, int buf) {
        const __half* Ag = A + (size_t)row0 * Kt + c * 64;
        const __half* Bg = B + c * 64;
        uint32_t ab = sbase + buf * 16384;
        uint32_t bb = sbase + 32768 + buf * NB;
        for (int i = tid; i < total; i += nthreads) {
            if (i < a_items) {
                int r = i >> 3, q = i & 7;
                if (row0 + r < M)
                    cp_async16(ab + SWZ((uint32_t)(r * 128 + q * 16)),
                               Ag + (size_t)r * Kt + q * 8);
            } else {
                int j = i - a_items;
                int r = j >> 3, q = j & 7;
                cp_async16(bb + SWZ((uint32_t)(r * 128 + q * 16)),
                           Bg + (size_t)r * Kt + q * 8);
            }
        }
        asm volatile("cp.async.commit_group;" ::: "memory");
    };

    load_chunk(0, 0);

    for (int c = 0; c < nch; c++) {
        int buf = c & 1;
        if (c + 1 < nch) {
            load_chunk(c + 1, (c + 1) & 1);
            asm volatile("cp.async.wait_group 1;" ::: "memory");
        } else {
            asm volatile("cp.async.wait_group 0;" ::: "memory");
        }
        __syncthreads();

        uint32_t ab = sbase + buf * 16384;
        uint32_t bb = sbase + 32768 + buf * NB;
#pragma unroll
        for (int k16 = 0; k16 < 4; k16++) {
            uint32_t a[2][4], b[4][4];
#pragma unroll
            for (int mf = 0; mf < 2; mf++) {
                uint32_t addr = ab + SWZ(a_off[mf] + (uint32_t)(k16 * 32));
                asm volatile("ldmatrix.sync.aligned.m8n8.x4.shared.b16 {%0,%1,%2,%3}, [%4];"
                             : "=r"(a[mf][0]), "=r"(a[mf][1]), "=r"(a[mf][2]), "=r"(a[mf][3])
                             : "r"(addr));
            }
#pragma unroll
            for (int nf4 = 0; nf4 < 4; nf4++) {
                uint32_t addr = bb + SWZ(b_off[nf4] + (uint32_t)(k16 * 32));
                asm volatile("ldmatrix.sync.aligned.m8n8.x4.shared.b16 {%0,%1,%2,%3}, [%4];"
                             : "=r"(b[nf4][0]), "=r"(b[nf4][1]), "=r"(b[nf4][2]), "=r"(b[nf4][3])
                             : "r"(addr));
            }
#pragma unroll
            for (int mf = 0; mf < 2; mf++)
#pragma unroll
                for (int nf = 0; nf < 8; nf++) {
                    asm volatile(
                        "mma.sync.aligned.m16n8k16.row.col.f32.f16.f16.f32 "
                        "{%0,%1,%2,%3}, {%4,%5,%6,%7}, {%8,%9}, {%0,%1,%2,%3};"
                        : "+f"(acc[mf][nf][0]), "+f"(acc[mf][nf][1]),
                          "+f"(acc[mf][nf][2]), "+f"(acc[mf][nf][3])
                        : "r"(a[mf][0]), "r"(a[mf][1]), "r"(a[mf][2]), "r"(a[mf][3]),
                          "r"(b[nf >> 1][(nf & 1) * 2]), "r"(b[nf >> 1][(nf & 1) * 2 + 1]));
                }
        }
        __syncthreads();
    }

#pragma unroll
    for (int mf = 0; mf < 2; mf++) {
        int r0g = row0 + wm * 32 + mf * 16 + (lane >> 2);
        int r1g = r0g + 8;
#pragma unroll
        for (int nf = 0; nf < 8; nf++) {
            int col = wn * 64 + nf * 8 + (lane & 3) * 2;
            float2 v0 = make_float2(acc[mf][nf][0], acc[mf][nf][1]);
            float2 v1 = make_float2(acc[mf][nf][2], acc[mf][nf][3]);
            if (bias) {
                float bx = bias[col], by = bias[col + 1];
                v0.x += bx; v0.y += by;
                v1.x += bx; v1.y += by;
            }
            if (do_relu) {
                v0.x = fmaxf(v0.x, 0.f); v0.y = fmaxf(v0.y, 0.f);
                v1.x = fmaxf(v1.x, 0.f); v1.y = fmaxf(v1.y, 0.f);
            }
            if (r0g < M) *reinterpret_cast<float2*>(C + (size_t)r0g * N + col) = v0;
            if (r1g < M) *reinterpret_cast<float2*>(C + (size_t)r1g * N + col) = v1;
        }
    }
}

// ---------------- aggregation ----------------
__global__ void k_he_gather(const float* __restrict__ X, float* __restrict__ HE, int F4) {
    int e = blockIdx.x;
    int f = threadIdx.x;
    int s = g_he_off[e], t = g_he_off[e + 1];
    float4 acc = make_float4(0.f, 0.f, 0.f, 0.f);
    for (int j = s; j < t; j++) {
        int n = g_he_nodes[j];
        float4 v = reinterpret_cast<const float4*>(X)[(size_t)n * F4 + f];
        acc.x += v.x; acc.y += v.y; acc.z += v.z; acc.w += v.w;
    }
    float inv = (t > s) ? 1.0f / (float)(t - s) : 0.f;
    acc.x *= inv; acc.y *= inv; acc.z *= inv; acc.w *= inv;
    reinterpret_cast<float4*>(HE)[(size_t)e * F4 + f] = acc;
}

// node aggregation -> fp32 (bias!=null applies bias+relu)
__global__ void k_node_gather(const float* __restrict__ HE, const float* __restrict__ bias,
                              float* __restrict__ OUT, int F4) {
    int n = blockIdx.x;
    int f = threadIdx.x;
    int s = g_nd_off[n], t = g_nd_off[n + 1];
    float4 acc = make_float4(0.f, 0.f, 0.f, 0.f);
    for (int j = s; j < t; j++) {
        int e = g_nd_hes[j];
        float4 v = reinterpret_cast<const float4*>(HE)[(size_t)e * F4 + f];
        acc.x += v.x; acc.y += v.y; acc.z += v.z; acc.w += v.w;
    }
    float inv = (t > s) ? 1.0f / (float)(t - s) : 0.f;
    if (bias) {
        float4 b4 = reinterpret_cast<const float4*>(bias)[f];
        acc.x = fmaxf(fmaf(acc.x, inv, b4.x), 0.f);
        acc.y = fmaxf(fmaf(acc.y, inv, b4.y), 0.f);
        acc.z = fmaxf(fmaf(acc.z, inv, b4.z), 0.f);
        acc.w = fmaxf(fmaf(acc.w, inv, b4.w), 0.f);
    } else {
        acc.x *= inv; acc.y *= inv; acc.z *= inv; acc.w *= inv;
    }
    reinterpret_cast<float4*>(OUT)[(size_t)n * F4 + f] = acc;
}

// node aggregation -> split fp16 [hi(F)|lo(F)] directly (layer 1, no bias)
__global__ void k_node_gather_split(const float* __restrict__ HE,
                                    __half* __restrict__ Xs, int F) {
    int n = blockIdx.x;
    int f = threadIdx.x;               // F/4 threads
    int F4 = F >> 2;
    int s = g_nd_off[n], t = g_nd_off[n + 1];
    float4 acc = make_float4(0.f, 0.f, 0.f, 0.f);
    for (int j = s; j < t; j++) {
        int e = g_nd_hes[j];
        float4 v = reinterpret_cast<const float4*>(HE)[(size_t)e * F4 + f];
        acc.x += v.x; acc.y += v.y; acc.z += v.z; acc.w += v.w;
    }
    float inv = (t > s) ? 1.0f / (float)(t - s) : 0.f;
    acc.x *= inv; acc.y *= inv; acc.z *= inv; acc.w *= inv;

    uint32_t h0 = pack_hi2h(acc.x, acc.y);
    uint32_t h1 = pack_hi2h(acc.z, acc.w);
    uint32_t l0 = pack_lo2h(acc.x, acc.y, h0);
    uint32_t l1 = pack_lo2h(acc.z, acc.w, h1);
    __half* row = Xs + (size_t)n * 2 * F;
    int c = f * 4;
    *reinterpret_cast<uint2*>(row + c)     = make_uint2(h0, h1);
    *reinterpret_cast<uint2*>(row + F + c) = make_uint2(l0, l1);
}

// ---------------- batch norm ----------------
#define BN_ROWS_PER_BLOCK 250
__global__ void k_bn_stats(const float* __restrict__ X) {
    int f = threadIdx.x;
    int r0 = blockIdx.x * BN_ROWS_PER_BLOCK;
    float s = 0.f, ss = 0.f;
    for (int r = 0; r < BN_ROWS_PER_BLOCK; r++) {
        int row = r0 + r;
        if (row >= N_NODES) break;
        float v = X[(size_t)row * HID + f];
        s += v;
        ss += v * v;
    }
    atomicAdd(&g_sum[f], s);
    atomicAdd(&g_sumsq[f], ss);
}

// BN apply + 2-term fp16 split fused: X1 fp32 [N,256] -> Xs fp16 [N, 512] = [hi|lo]
__global__ void k_bn_apply_split(const float* __restrict__ X, __half* __restrict__ Xs,
                                 const float* __restrict__ g, const float* __restrict__ be) {
    int idx = blockIdx.x * blockDim.x + threadIdx.x;   // over N*64
    if (idx >= N_NODES * (HID / 4)) return;
    int f4 = idx & (HID / 4 - 1);
    int row = idx >> 6;
    float4 sm = reinterpret_cast<const float4*>(g_sum)[f4];
    float4 sq = reinterpret_cast<const float4*>(g_sumsq)[f4];
    float4 gg = reinterpret_cast<const float4*>(g)[f4];
    float4 bb = reinterpret_cast<const float4*>(be)[f4];
    const float invN = 1.0f / (float)N_NODES;
    float4 x = reinterpret_cast<const float4*>(X)[idx];
    float4 y;
    { float m = sm.x * invN; float v = sq.x * invN - m * m;
      float sc = gg.x * rsqrtf(v + BN_EPS); y.x = (x.x - m) * sc + bb.x; }
    { float m = sm.y * invN; float v = sq.y * invN - m * m;
      float sc = gg.y * rsqrtf(v + BN_EPS); y.y = (x.y - m) * sc + bb.y; }
    { float m = sm.z * invN; float v = sq.z * invN - m * m;
      float sc = gg.z * rsqrtf(v + BN_EPS); y.z = (x.z - m) * sc + bb.z; }
    { float m = sm.w * invN; float v = sq.w * invN - m * m;
      float sc = gg.w * rsqrtf(v + BN_EPS); y.w = (x.w - m) * sc + bb.w; }

    uint32_t h0 = pack_hi2h(y.x, y.y);
    uint32_t h1 = pack_hi2h(y.z, y.w);
    uint32_t l0 = pack_lo2h(y.x, y.y, h0);
    uint32_t l1 = pack_lo2h(y.z, y.w, h1);
    __half* orow = Xs + (size_t)row * (2 * HID);
    int c = f4 * 4;
    *reinterpret_cast<uint2*>(orow + c)       = make_uint2(h0, h1);
    *reinterpret_cast<uint2*>(orow + HID + c) = make_uint2(l0, l1);
}

// ---------------- launch ----------------
extern "C" void kernel_launch(void* const* d_in, const int* in_sizes, int n_in,
                              void* d_out, int out_size) {
    const float* x    = (const float*)d_in[0];
    const int*   edge = (const int*)d_in[1];
    const int*   node_idx = edge;
    const int*   he_idx   = edge + N_INC;
    const float* W1 = (const float*)d_in[2];
    const float* b1 = (const float*)d_in[3];
    const float* g1 = (const float*)d_in[4];
    const float* be1 = (const float*)d_in[5];
    const float* W2 = (const float*)d_in[6];
    const float* b2 = (const float*)d_in[7];
    const float* g2 = (const float*)d_in[8];
    const float* be2 = (const float*)d_in[9];
    const float* W3 = (const float*)d_in[10];
    const float* b3 = (const float*)d_in[11];
    float* out = (float*)d_out;

    void *p_X1, *p_HE, *p_Xs, *p_W1s, *p_W2s, *p_W3s;
    void *p_nd_cnt, *p_he_cnt, *p_sum, *p_sumsq, *p_nd_off, *p_he_off, *p_bsum;
    cudaGetSymbolAddress(&p_X1, g_X1);
    cudaGetSymbolAddress(&p_HE, g_HE);
    cudaGetSymbolAddress(&p_Xs, g_Xs);
    cudaGetSymbolAddress(&p_W1s, g_W1s);
    cudaGetSymbolAddress(&p_W2s, g_W2s);
    cudaGetSymbolAddress(&p_W3s, g_W3s);
    cudaGetSymbolAddress(&p_nd_cnt, g_nd_cnt);
    cudaGetSymbolAddress(&p_he_cnt, g_he_cnt);
    cudaGetSymbolAddress(&p_sum, g_sum);
    cudaGetSymbolAddress(&p_sumsq, g_sumsq);
    cudaGetSymbolAddress(&p_nd_off, g_nd_off);
    cudaGetSymbolAddress(&p_he_off, g_he_off);
    cudaGetSymbolAddress(&p_bsum, g_bsum);
    float* X1 = (float*)p_X1;
    float* HE = (float*)p_HE;
    __half* Xs  = (__half*)p_Xs;
    __half* W1s = (__half*)p_W1s;
    __half* W2s = (__half*)p_W2s;
    __half* W3s = (__half*)p_W3s;
    int* bsum = (int*)p_bsum;

    const int GEMM_SMEM = 98304;   // 2x16KB A + 2x32KB B (N=256)
    cudaFuncSetAttribute(gemm_f16_mma, cudaFuncAttributeMaxDynamicSharedMemorySize, GEMM_SMEM);
    const int mtiles = (N_NODES + 127) / 128;   // 782

    // ---- weight splits (independent, up front) ----
    k_split_W<<<(IN_CH * HID + 255) / 256, 256>>>(W1, W1s, IN_CH, HID);
    k_split_W<<<(HID * HID + 255) / 256, 256>>>(W2, W2s, HID, HID);
    k_split_W<<<(HID * OUT_CH + 255) / 256, 256>>>(W3, W3s, HID, OUT_CH);

    // ---- CSR build ----
    cudaMemsetAsync(p_nd_cnt, 0, N_NODES * sizeof(int));
    cudaMemsetAsync(p_he_cnt, 0, N_HE * sizeof(int));
    k_hist<<<(N_INC + 255) / 256, 256>>>(node_idx, he_idx);
    const int nb_nd = (N_NODES + 2047) / 2048;   // 49
    const int nb_he = (N_HE + 2047) / 2048;      // 15
    k_blk_sum<<<nb_nd, 256>>>((const int*)p_nd_cnt, bsum, N_NODES);
    k_bsum_scan<<<1, 1024>>>(bsum, (int*)p_nd_off, nb_nd, N_NODES);
    k_blk_scan<<<nb_nd, 256>>>((const int*)p_nd_cnt, bsum, (int*)p_nd_off, N_NODES);
    k_blk_sum<<<nb_he, 256>>>((const int*)p_he_cnt, bsum, N_HE);
    k_bsum_scan<<<1, 1024>>>(bsum, (int*)p_he_off, nb_he, N_HE);
    k_blk_scan<<<nb_he, 256>>>((const int*)p_he_cnt, bsum, (int*)p_he_off, N_HE);
    cudaMemsetAsync(p_nd_cnt, 0, N_NODES * sizeof(int));
    cudaMemsetAsync(p_he_cnt, 0, N_HE * sizeof(int));
    k_scatter<<<(N_INC + 255) / 256, 256>>>(node_idx, he_idx);

    const int bn_grid = (N_NODES + BN_ROWS_PER_BLOCK - 1) / BN_ROWS_PER_BLOCK;
    const int apply_grid = (N_NODES * (HID / 4) + 255) / 256;

    // ---- layer 1: aggregate FIRST at 128 ch (A(xW)=(Ax)W), split fused into gather ----
    {
        k_he_gather<<<N_HE, IN_CH / 4>>>(x, HE, IN_CH / 4);
        k_node_gather_split<<<N_NODES, IN_CH / 4>>>(HE, Xs, IN_CH);   // -> Xs [M, 256]=[hi|lo]
        dim3 grid(1, mtiles);
        gemm_f16_mma<<<grid, 512, GEMM_SMEM>>>(Xs, W1s, X1, N_NODES, 2 * IN_CH, HID, b1, 1);
        cudaMemsetAsync(p_sum, 0, HID * sizeof(float));
        cudaMemsetAsync(p_sumsq, 0, HID * sizeof(float));
        k_bn_stats<<<bn_grid, HID>>>(X1);
        k_bn_apply_split<<<apply_grid, 256>>>(X1, Xs, g1, be1);       // -> Xs [M, 512]
    }
    // ---- layer 2 ----
    {
        dim3 grid(1, mtiles);
        gemm_f16_mma<<<grid, 512, GEMM_SMEM>>>(Xs, W2s, X1, N_NODES, 2 * HID, HID, nullptr, 0);
        k_he_gather<<<N_HE, HID / 4>>>(X1, HE, HID / 4);
        k_node_gather<<<N_NODES, HID / 4>>>(HE, b2, X1, HID / 4);
        cudaMemsetAsync(p_sum, 0, HID * sizeof(float));
        cudaMemsetAsync(p_sumsq, 0, HID * sizeof(float));
        k_bn_stats<<<bn_grid, HID>>>(X1);
        k_bn_apply_split<<<apply_grid, 256>>>(X1, Xs, g2, be2);       // -> Xs [M, 512]
    }
    // ---- layer 3 ----
    {
        dim3 grid(1, mtiles);
        gemm_f16_mma<<<grid, 256, GEMM_SMEM>>>(Xs, W3s, X1, N_NODES, 2 * HID, OUT_CH, nullptr, 0);
        k_he_gather<<<N_HE, OUT_CH / 4>>>(X1, HE, OUT_CH / 4);
        k_node_gather<<<N_NODES, OUT_CH / 4>>>(HE, b3, out, OUT_CH / 4);
    }
}

// round 8
// speedup vs baseline: 1.5066x; 1.0681x over previous
#include <cuda_runtime.h>
#include <cuda_bf16.h>
#include <cuda_fp16.h>
#include <cstdint>

#define N_NODES 100000
#define N_HE    30000
#define N_INC   300000
#define IN_CH   128
#define HID     256
#define OUT_CH  128
#define BN_EPS  1e-5f

// ---------------- device scratch (allocation-free) ----------------
__device__ float g_X1[(size_t)N_NODES * HID];   // fp32 staging A
__device__ float g_X2[(size_t)N_NODES * HID];   // fp32 staging B (GEMM out for L2/L3)
__device__ float g_HE[(size_t)N_HE   * HID];    // hyperedge features
__device__ __half g_Xs[(size_t)N_NODES * 2 * IN_CH];  // L1 split activations [M, 2K]
__device__ __half g_W1s[(size_t)HID * 2 * IN_CH];
__device__ __half g_W2s[(size_t)HID * 2 * HID];
__device__ __half g_W3s[(size_t)OUT_CH * 2 * HID];

__device__ int g_nd_cnt[N_NODES];
__device__ int g_he_cnt[N_HE];
__device__ int g_nd_off[N_NODES + 1];
__device__ int g_he_off[N_HE + 1];
__device__ int g_nd_hes[N_INC];
__device__ int g_he_nodes[N_INC];
__device__ int g_bsum[128];

__device__ float g_sum[HID];
__device__ float g_sumsq[HID];

// ---------------- helpers ----------------
__device__ __forceinline__ uint32_t smem_to_u32(const void* p) {
    uint32_t a;
    asm("{ .reg .u64 t; cvta.to.shared.u64 t, %1; cvt.u32.u64 %0, t; }" : "=r"(a) : "l"(p));
    return a;
}
#define SWZ(off) ((off) ^ (((off) >> 3) & 0x70))

__device__ __forceinline__ void cp_async16(uint32_t dst, const void* src) {
    asm volatile("cp.async.cg.shared.global [%0], [%1], 16;" :: "r"(dst), "l"(src) : "memory");
}

__device__ __forceinline__ uint32_t pack_hi2h(float x, float y) {
    __half2 h = __floats2half2_rn(x, y);
    return *reinterpret_cast<uint32_t*>(&h);
}
__device__ __forceinline__ uint32_t pack_lo2h(float x, float y, uint32_t hi2) {
    __half2 h = *reinterpret_cast<__half2*>(&hi2);
    __half2 l = __floats2half2_rn(x - __half2float(h.x), y - __half2float(h.y));
    return *reinterpret_cast<uint32_t*>(&l);
}

// ---------------- CSR build ----------------
__global__ void k_hist(const int* __restrict__ node_idx, const int* __restrict__ he_idx) {
    int i = blockIdx.x * blockDim.x + threadIdx.x;
    if (i < N_INC) {
        atomicAdd(&g_nd_cnt[node_idx[i]], 1);
        atomicAdd(&g_he_cnt[he_idx[i]], 1);
    }
}

// combined nd+he multi-block scan
__global__ void k_blk_sum2(int nb_nd) {
    bool he = (int)blockIdx.x >= nb_nd;
    const int* cnt = he ? g_he_cnt : g_nd_cnt;
    int n = he ? N_HE : N_NODES;
    int bid = he ? blockIdx.x - nb_nd : blockIdx.x;
    int* bs = g_bsum + (he ? 64 : 0);
    int tid = threadIdx.x;
    int base = bid * 2048;
    int s = 0;
#pragma unroll
    for (int i = 0; i < 8; i++) {
        int idx = base + i * 256 + tid;
        if (idx < n) s += cnt[idx];
    }
#pragma unroll
    for (int o = 16; o > 0; o >>= 1) s += __shfl_xor_sync(0xFFFFFFFFu, s, o);
    __shared__ int ws[8];
    if ((tid & 31) == 0) ws[tid >> 5] = s;
    __syncthreads();
    if (tid == 0) {
        int t = 0;
#pragma unroll
        for (int w = 0; w < 8; w++) t += ws[w];
        bs[bid] = t;
    }
}
__global__ void k_bsum_scan2(int nb_nd, int nb_he) {
    bool he = blockIdx.x == 1;
    int nb = he ? nb_he : nb_nd;
    int* bs = g_bsum + (he ? 64 : 0);
    int* off = he ? g_he_off : g_nd_off;
    int n = he ? N_HE : N_NODES;
    int tid = threadIdx.x;
    int lane = tid & 31, w = tid >> 5;
    int v = (tid < nb) ? bs[tid] : 0;
    int x = v;
#pragma unroll
    for (int o = 1; o < 32; o <<= 1) {
        int t = __shfl_up_sync(0xFFFFFFFFu, x, o);
        if (lane >= o) x += t;
    }
    __shared__ int ws[32];
    if (lane == 31) ws[w] = x;
    __syncthreads();
    if (w == 0) {
        int y = ws[lane];
        int z = y;
#pragma unroll
        for (int o = 1; o < 32; o <<= 1) {
            int t = __shfl_up_sync(0xFFFFFFFFu, z, o);
            if (lane >= o) z += t;
        }
        ws[lane] = z - y;
    }
    __syncthreads();
    int excl = x - v + ws[w];
    if (tid < nb) bs[tid] = excl;
    if (tid == nb - 1) off[n] = excl + v;
}
__global__ void k_blk_scan2(int nb_nd) {
    bool he = (int)blockIdx.x >= nb_nd;
    const int* cnt = he ? g_he_cnt : g_nd_cnt;
    int n = he ? N_HE : N_NODES;
    int bid = he ? blockIdx.x - nb_nd : blockIdx.x;
    const int* bs = g_bsum + (he ? 64 : 0);
    int* off = he ? g_he_off : g_nd_off;
    int tid = threadIdx.x;
    int base = bid * 2048;
    int v[8];
    int s = 0;
#pragma unroll
    for (int i = 0; i < 8; i++) {
        int idx = base + tid * 8 + i;
        v[i] = (idx < n) ? cnt[idx] : 0;
        s += v[i];
    }
    int lane = tid & 31, w = tid >> 5;
    int x = s;
#pragma unroll
    for (int o = 1; o < 32; o <<= 1) {
        int t = __shfl_up_sync(0xFFFFFFFFu, x, o);
        if (lane >= o) x += t;
    }
    __shared__ int ws[8];
    __shared__ int wexcl[8];
    if (lane == 31) ws[w] = x;
    __syncthreads();
    if (tid < 8) {
        int t = 0;
        for (int j = 0; j < tid; j++) t += ws[j];
        wexcl[tid] = t;
    }
    __syncthreads();
    int run = bs[bid] + wexcl[w] + (x - s);
#pragma unroll
    for (int i = 0; i < 8; i++) {
        int idx = base + tid * 8 + i;
        if (idx < n) off[idx] = run;
        run += v[i];
    }
}

__global__ void k_scatter(const int* __restrict__ node_idx, const int* __restrict__ he_idx) {
    int i = blockIdx.x * blockDim.x + threadIdx.x;
    if (i < N_INC) {
        int n = node_idx[i], e = he_idx[i];
        int p = atomicAdd(&g_he_cnt[e], 1);
        g_he_nodes[g_he_off[e] + p] = n;
        int q = atomicAdd(&g_nd_cnt[n], 1);
        g_nd_hes[g_nd_off[n] + q] = e;
    }
}

// ---------------- weight split ----------------
// W [K,N] fp32 -> Ws [N, 2K] fp16 (transposed), row layout [hi(K) | lo(K)]
__global__ void k_split_W(const float* __restrict__ W, __half* __restrict__ Ws, int K, int N) {
    int i = blockIdx.x * blockDim.x + threadIdx.x;
    if (i >= K * N) return;
    int k = i / N, n = i - k * N;
    float v = W[i];
    __half h = __float2half_rn(v);
    __half l = __float2half_rn(v - __half2float(h));
    __half* O = Ws + (size_t)n * 2 * K;
    O[k] = h;
    O[K + k] = l;
}

// ---------------- GEMM 1 (fp16 A precomputed): C = A[M,Kt] @ B[N,Kt]^T ----------------
__global__ void __launch_bounds__(512, 1)
gemm_f16_mma(const __half* __restrict__ A, const __half* __restrict__ B,
             float* __restrict__ C, int M, int Kt, int N,
             const float* __restrict__ bias, int do_relu)
{
    extern __shared__ char smc[];
    const uint32_t sbase = smem_to_u32(smc);
    const int tid  = threadIdx.x;
    const int lane = tid & 31;
    const int wid  = tid >> 5;
    const int nwn  = N >> 6;
    const int wm   = wid / nwn;
    const int wn   = wid % nwn;
    const int row0 = blockIdx.y * 128;
    const int nthreads = nwn * 4 * 32;

    const int nch = Kt >> 6;
    const uint32_t NB = (uint32_t)N * 128;

    float acc[2][8][4];
#pragma unroll
    for (int i = 0; i < 2; i++)
#pragma unroll
        for (int j = 0; j < 8; j++)
#pragma unroll
            for (int k = 0; k < 4; k++) acc[i][j][k] = 0.f;

    uint32_t a_off[2], b_off[4];
#pragma unroll
    for (int mf = 0; mf < 2; mf++)
        a_off[mf] = (uint32_t)((wm * 32 + mf * 16 + (lane & 15)) * 128 + (lane >> 4) * 16);
#pragma unroll
    for (int nf4 = 0; nf4 < 4; nf4++)
        b_off[nf4] = (uint32_t)((wn * 64 + nf4 * 16 + (lane & 7) + ((lane >> 4) & 1) * 8) * 128
                                + ((lane >> 3) & 1) * 16);

    const int a_items = 1024;
    const int total = a_items + N * 8;

    auto load_chunk = [&](int c, int buf) {
        const __half* Ag = A + (size_t)row0 * Kt + c * 64;
        const __half* Bg = B + c * 64;
        uint32_t ab = sbase + buf * 16384;
        uint32_t bb = sbase + 32768 + buf * NB;
        for (int i = tid; i < total; i += nthreads) {
            if (i < a_items) {
                int r = i >> 3, q = i & 7;
                if (row0 + r < M)
                    cp_async16(ab + SWZ((uint32_t)(r * 128 + q * 16)),
                               Ag + (size_t)r * Kt + q * 8);
            } else {
                int j = i - a_items;
                int r = j >> 3, q = j & 7;
                cp_async16(bb + SWZ((uint32_t)(r * 128 + q * 16)),
                           Bg + (size_t)r * Kt + q * 8);
            }
        }
        asm volatile("cp.async.commit_group;" ::: "memory");
    };

    load_chunk(0, 0);

    for (int c = 0; c < nch; c++) {
        int buf = c & 1;
        if (c + 1 < nch) {
            load_chunk(c + 1, (c + 1) & 1);
            asm volatile("cp.async.wait_group 1;" ::: "memory");
        } else {
            asm volatile("cp.async.wait_group 0;" ::: "memory");
        }
        __syncthreads();

        uint32_t ab = sbase + buf * 16384;
        uint32_t bb = sbase + 32768 + buf * NB;
#pragma unroll
        for (int k16 = 0; k16 < 4; k16++) {
            uint32_t a[2][4], b[4][4];
#pragma unroll
            for (int mf = 0; mf < 2; mf++) {
                uint32_t addr = ab + SWZ(a_off[mf] + (uint32_t)(k16 * 32));
                asm volatile("ldmatrix.sync.aligned.m8n8.x4.shared.b16 {%0,%1,%2,%3}, [%4];"
                             : "=r"(a[mf][0]), "=r"(a[mf][1]), "=r"(a[mf][2]), "=r"(a[mf][3])
                             : "r"(addr));
            }
#pragma unroll
            for (int nf4 = 0; nf4 < 4; nf4++) {
                uint32_t addr = bb + SWZ(b_off[nf4] + (uint32_t)(k16 * 32));
                asm volatile("ldmatrix.sync.aligned.m8n8.x4.shared.b16 {%0,%1,%2,%3}, [%4];"
                             : "=r"(b[nf4][0]), "=r"(b[nf4][1]), "=r"(b[nf4][2]), "=r"(b[nf4][3])
                             : "r"(addr));
            }
#pragma unroll
            for (int mf = 0; mf < 2; mf++)
#pragma unroll
                for (int nf = 0; nf < 8; nf++) {
                    asm volatile(
                        "mma.sync.aligned.m16n8k16.row.col.f32.f16.f16.f32 "
                        "{%0,%1,%2,%3}, {%4,%5,%6,%7}, {%8,%9}, {%0,%1,%2,%3};"
                        : "+f"(acc[mf][nf][0]), "+f"(acc[mf][nf][1]),
                          "+f"(acc[mf][nf][2]), "+f"(acc[mf][nf][3])
                        : "r"(a[mf][0]), "r"(a[mf][1]), "r"(a[mf][2]), "r"(a[mf][3]),
                          "r"(b[nf >> 1][(nf & 1) * 2]), "r"(b[nf >> 1][(nf & 1) * 2 + 1]));
                }
        }
        __syncthreads();
    }

#pragma unroll
    for (int mf = 0; mf < 2; mf++) {
        int r0g = row0 + wm * 32 + mf * 16 + (lane >> 2);
        int r1g = r0g + 8;
#pragma unroll
        for (int nf = 0; nf < 8; nf++) {
            int col = wn * 64 + nf * 8 + (lane & 3) * 2;
            float2 v0 = make_float2(acc[mf][nf][0], acc[mf][nf][1]);
            float2 v1 = make_float2(acc[mf][nf][2], acc[mf][nf][3]);
            if (bias) {
                float bx = bias[col], by = bias[col + 1];
                v0.x += bx; v0.y += by;
                v1.x += bx; v1.y += by;
            }
            if (do_relu) {
                v0.x = fmaxf(v0.x, 0.f); v0.y = fmaxf(v0.y, 0.f);
                v1.x = fmaxf(v1.x, 0.f); v1.y = fmaxf(v1.y, 0.f);
            }
            if (r0g < M) *reinterpret_cast<float2*>(C + (size_t)r0g * N + col) = v0;
            if (r1g < M) *reinterpret_cast<float2*>(C + (size_t)r1g * N + col) = v1;
        }
    }
}

// ---------------- GEMM 2: BN+split fused into A-path ----------------
// A = fp32 X [M,K]; per-column BN (scale/shift from g_sum/g_sumsq + gamma/beta)
// applied on load, then 2-term fp16 split in registers -> smem hi/lo tiles.
// B = fp16 [N, 2K] ([hi|lo]). C fp32, no bias/relu. K must be 256 here.
// smem: sc[256]@0, sh[256]@1024, tiles from 2048:
//   stage s: Ahi @ s*STAGE, Alo @ +16384, B(hi chunk) @ +32768, B(lo chunk) @ +32768+NB
template <int NWN>
__global__ void __launch_bounds__(NWN * 128, 1)
gemm_bn_f16(const float* __restrict__ A, const __half* __restrict__ Bw,
            float* __restrict__ C, int M, int K,
            const float* __restrict__ bn_s, const float* __restrict__ bn_q,
            const float* __restrict__ gam, const float* __restrict__ bet)
{
    constexpr int N = NWN * 64;
    constexpr int NT = NWN * 128;
    constexpr uint32_t NB = (uint32_t)N * 128;
    constexpr uint32_t STAGE = 32768 + 2 * NB;
    extern __shared__ char smc[];
    const uint32_t sbase = smem_to_u32(smc);
    const uint32_t tbase = sbase + 2048;
    const int tid  = threadIdx.x;
    const int lane = tid & 31;
    const int wid  = tid >> 5;
    const int wm   = wid / NWN;
    const int wn   = wid % NWN;
    const int row0 = blockIdx.y * 128;
    const int K64  = K >> 6;       // physical fp32 chunks
    const int Kt   = 2 * K;        // B row stride (fp16)

    float* sc = reinterpret_cast<float*>(smc);
    float* sh = reinterpret_cast<float*>(smc + 1024);
    if (tid < K) {
        const float invN = 1.0f / (float)N_NODES;
        float m = bn_s[tid] * invN;
        float v = bn_q[tid] * invN - m * m;
        float s = gam[tid] * rsqrtf(v + BN_EPS);
        sc[tid] = s;
        sh[tid] = bet[tid] - m * s;
    }
    __syncthreads();

    float acc[2][8][4];
#pragma unroll
    for (int i = 0; i < 2; i++)
#pragma unroll
        for (int j = 0; j < 8; j++)
#pragma unroll
            for (int k = 0; k < 4; k++) acc[i][j][k] = 0.f;

    uint32_t a_off[2], b_off[4];
#pragma unroll
    for (int mf = 0; mf < 2; mf++)
        a_off[mf] = (uint32_t)((wm * 32 + mf * 16 + (lane & 15)) * 128 + (lane >> 4) * 16);
#pragma unroll
    for (int nf4 = 0; nf4 < 4; nf4++)
        b_off[nf4] = (uint32_t)((wn * 64 + nf4 * 16 + (lane & 7) + ((lane >> 4) & 1) * 8) * 128
                                + ((lane >> 3) & 1) * 16);

    constexpr int AITERS = 1024 / NT;   // 8-col items per thread
    float4 af[AITERS * 2];

    auto loadA = [&](int c) {
#pragma unroll
        for (int it = 0; it < AITERS; it++) {
            int j = tid + it * NT;
            int r = j >> 3, q8 = j & 7;
            if (row0 + r < M) {
                const float* src = A + (size_t)(row0 + r) * K + c * 64 + q8 * 8;
                af[it * 2]     = *reinterpret_cast<const float4*>(src);
                af[it * 2 + 1] = *reinterpret_cast<const float4*>(src + 4);
            } else {
                af[it * 2] = make_float4(0.f, 0.f, 0.f, 0.f);
                af[it * 2 + 1] = make_float4(0.f, 0.f, 0.f, 0.f);
            }
        }
    };
    auto storeA = [&](int c, int buf) {
#pragma unroll
        for (int it = 0; it < AITERS; it++) {
            int j = tid + it * NT;
            int r = j >> 3, q8 = j & 7;
            int col0 = c * 64 + q8 * 8;
            float y[8];
            const float* a0 = reinterpret_cast<const float*>(&af[it * 2]);
#pragma unroll
            for (int u = 0; u < 8; u++)
                y[u] = a0[u] * sc[col0 + u] + sh[col0 + u];
            uint32_t h01 = pack_hi2h(y[0], y[1]);
            uint32_t h23 = pack_hi2h(y[2], y[3]);
            uint32_t h45 = pack_hi2h(y[4], y[5]);
            uint32_t h67 = pack_hi2h(y[6], y[7]);
            uint32_t l01 = pack_lo2h(y[0], y[1], h01);
            uint32_t l23 = pack_lo2h(y[2], y[3], h23);
            uint32_t l45 = pack_lo2h(y[4], y[5], h45);
            uint32_t l67 = pack_lo2h(y[6], y[7], h67);
            uint32_t off = SWZ((uint32_t)(r * 128 + q8 * 16));
            char* base = smc + 2048 + buf * STAGE;
            *reinterpret_cast<uint4*>(base + off) = make_uint4(h01, h23, h45, h67);
            *reinterpret_cast<uint4*>(base + 16384 + off) = make_uint4(l01, l23, l45, l67);
        }
    };
    auto loadB = [&](int c, int buf) {
        uint32_t bb = tbase + buf * STAGE + 32768;
#pragma unroll
        for (int t = 0; t < 2; t++) {
            int cb = c + t * K64;   // logical chunk: hi region then lo region
            const __half* Bg = Bw + cb * 64;
            for (int i = tid; i < N * 8; i += NT) {
                int r = i >> 3, q = i & 7;
                cp_async16(bb + t * NB + SWZ((uint32_t)(r * 128 + q * 16)),
                           Bg + (size_t)r * Kt + q * 8);
            }
        }
        asm volatile("cp.async.commit_group;" ::: "memory");
    };
    auto mmaStage = [&](int buf) {
#pragma unroll
        for (int t = 0; t < 2; t++) {
            uint32_t ab = tbase + buf * STAGE + t * 16384;
            uint32_t bb = tbase + buf * STAGE + 32768 + t * NB;
#pragma unroll
            for (int k16 = 0; k16 < 4; k16++) {
                uint32_t a[2][4], b[4][4];
#pragma unroll
                for (int mf = 0; mf < 2; mf++) {
                    uint32_t addr = ab + SWZ(a_off[mf] + (uint32_t)(k16 * 32));
                    asm volatile("ldmatrix.sync.aligned.m8n8.x4.shared.b16 {%0,%1,%2,%3}, [%4];"
                                 : "=r"(a[mf][0]), "=r"(a[mf][1]), "=r"(a[mf][2]), "=r"(a[mf][3])
                                 : "r"(addr));
                }
#pragma unroll
                for (int nf4 = 0; nf4 < 4; nf4++) {
                    uint32_t addr = bb + SWZ(b_off[nf4] + (uint32_t)(k16 * 32));
                    asm volatile("ldmatrix.sync.aligned.m8n8.x4.shared.b16 {%0,%1,%2,%3}, [%4];"
                                 : "=r"(b[nf4][0]), "=r"(b[nf4][1]), "=r"(b[nf4][2]), "=r"(b[nf4][3])
                                 : "r"(addr));
                }
#pragma unroll
                for (int mf = 0; mf < 2; mf++)
#pragma unroll
                    for (int nf = 0; nf < 8; nf++) {
                        asm volatile(
                            "mma.sync.aligned.m16n8k16.row.col.f32.f16.f16.f32 "
                            "{%0,%1,%2,%3}, {%4,%5,%6,%7}, {%8,%9}, {%0,%1,%2,%3};"
                            : "+f"(acc[mf][nf][0]), "+f"(acc[mf][nf][1]),
                              "+f"(acc[mf][nf][2]), "+f"(acc[mf][nf][3])
                            : "r"(a[mf][0]), "r"(a[mf][1]), "r"(a[mf][2]), "r"(a[mf][3]),
                              "r"(b[nf >> 1][(nf & 1) * 2]), "r"(b[nf >> 1][(nf & 1) * 2 + 1]));
                    }
            }
        }
    };

    // prologue
    loadA(0);
    loadB(0, 0);
    storeA(0, 0);
    asm volatile("cp.async.wait_group 0;" ::: "memory");
    __syncthreads();

    for (int c = 0; c < K64; c++) {
        int buf = c & 1;
        if (c + 1 < K64) {
            loadA(c + 1);
            loadB(c + 1, buf ^ 1);
        }
        mmaStage(buf);
        if (c + 1 < K64) {
            storeA(c + 1, buf ^ 1);
            asm volatile("cp.async.wait_group 0;" ::: "memory");
        }
        __syncthreads();
    }

    // epilogue (no bias / relu)
#pragma unroll
    for (int mf = 0; mf < 2; mf++) {
        int r0g = row0 + wm * 32 + mf * 16 + (lane >> 2);
        int r1g = r0g + 8;
#pragma unroll
        for (int nf = 0; nf < 8; nf++) {
            int col = wn * 64 + nf * 8 + (lane & 3) * 2;
            float2 v0 = make_float2(acc[mf][nf][0], acc[mf][nf][1]);
            float2 v1 = make_float2(acc[mf][nf][2], acc[mf][nf][3]);
            if (r0g < M) *reinterpret_cast<float2*>(C + (size_t)r0g * N + col) = v0;
            if (r1g < M) *reinterpret_cast<float2*>(C + (size_t)r1g * N + col) = v1;
        }
    }
}

// ---------------- aggregation ----------------
__global__ void k_he_gather(const float* __restrict__ X, float* __restrict__ HE, int F4) {
    int e = blockIdx.x;
    int f = threadIdx.x;
    int s = g_he_off[e], t = g_he_off[e + 1];
    float4 acc = make_float4(0.f, 0.f, 0.f, 0.f);
    for (int j = s; j < t; j++) {
        int n = g_he_nodes[j];
        float4 v = reinterpret_cast<const float4*>(X)[(size_t)n * F4 + f];
        acc.x += v.x; acc.y += v.y; acc.z += v.z; acc.w += v.w;
    }
    float inv = (t > s) ? 1.0f / (float)(t - s) : 0.f;
    acc.x *= inv; acc.y *= inv; acc.z *= inv; acc.w *= inv;
    reinterpret_cast<float4*>(HE)[(size_t)e * F4 + f] = acc;
}

__global__ void k_node_gather(const float* __restrict__ HE, const float* __restrict__ bias,
                              float* __restrict__ OUT, int F4) {
    int n = blockIdx.x;
    int f = threadIdx.x;
    int s = g_nd_off[n], t = g_nd_off[n + 1];
    float4 acc = make_float4(0.f, 0.f, 0.f, 0.f);
    for (int j = s; j < t; j++) {
        int e = g_nd_hes[j];
        float4 v = reinterpret_cast<const float4*>(HE)[(size_t)e * F4 + f];
        acc.x += v.x; acc.y += v.y; acc.z += v.z; acc.w += v.w;
    }
    float inv = (t > s) ? 1.0f / (float)(t - s) : 0.f;
    if (bias) {
        float4 b4 = reinterpret_cast<const float4*>(bias)[f];
        acc.x = fmaxf(fmaf(acc.x, inv, b4.x), 0.f);
        acc.y = fmaxf(fmaf(acc.y, inv, b4.y), 0.f);
        acc.z = fmaxf(fmaf(acc.z, inv, b4.z), 0.f);
        acc.w = fmaxf(fmaf(acc.w, inv, b4.w), 0.f);
    } else {
        acc.x *= inv; acc.y *= inv; acc.z *= inv; acc.w *= inv;
    }
    reinterpret_cast<float4*>(OUT)[(size_t)n * F4 + f] = acc;
}

// node aggregation -> split fp16 [hi(F)|lo(F)] (layer 1, no bias)
__global__ void k_node_gather_split(const float* __restrict__ HE,
                                    __half* __restrict__ Xs, int F) {
    int n = blockIdx.x;
    int f = threadIdx.x;
    int F4 = F >> 2;
    int s = g_nd_off[n], t = g_nd_off[n + 1];
    float4 acc = make_float4(0.f, 0.f, 0.f, 0.f);
    for (int j = s; j < t; j++) {
        int e = g_nd_hes[j];
        float4 v = reinterpret_cast<const float4*>(HE)[(size_t)e * F4 + f];
        acc.x += v.x; acc.y += v.y; acc.z += v.z; acc.w += v.w;
    }
    float inv = (t > s) ? 1.0f / (float)(t - s) : 0.f;
    acc.x *= inv; acc.y *= inv; acc.z *= inv; acc.w *= inv;

    uint32_t h0 = pack_hi2h(acc.x, acc.y);
    uint32_t h1 = pack_hi2h(acc.z, acc.w);
    uint32_t l0 = pack_lo2h(acc.x, acc.y, h0);
    uint32_t l1 = pack_lo2h(acc.z, acc.w, h1);
    __half* row = Xs + (size_t)n * 2 * F;
    int c = f * 4;
    *reinterpret_cast<uint2*>(row + c)     = make_uint2(h0, h1);
    *reinterpret_cast<uint2*>(row + F + c) = make_uint2(l0, l1);
}

// ---------------- batch norm stats ----------------
#define BN_ROWS_PER_BLOCK 250
__global__ void k_bn_stats(const float* __restrict__ X) {
    int f = threadIdx.x;
    int r0 = blockIdx.x * BN_ROWS_PER_BLOCK;
    float s = 0.f, ss = 0.f;
    for (int r = 0; r < BN_ROWS_PER_BLOCK; r++) {
        int row = r0 + r;
        if (row >= N_NODES) break;
        float v = X[(size_t)row * HID + f];
        s += v;
        ss += v * v;
    }
    atomicAdd(&g_sum[f], s);
    atomicAdd(&g_sumsq[f], ss);
}

// ---------------- launch ----------------
extern "C" void kernel_launch(void* const* d_in, const int* in_sizes, int n_in,
                              void* d_out, int out_size) {
    const float* x    = (const float*)d_in[0];
    const int*   edge = (const int*)d_in[1];
    const int*   node_idx = edge;
    const int*   he_idx   = edge + N_INC;
    const float* W1 = (const float*)d_in[2];
    const float* b1 = (const float*)d_in[3];
    const float* g1 = (const float*)d_in[4];
    const float* be1 = (const float*)d_in[5];
    const float* W2 = (const float*)d_in[6];
    const float* b2 = (const float*)d_in[7];
    const float* g2 = (const float*)d_in[8];
    const float* be2 = (const float*)d_in[9];
    const float* W3 = (const float*)d_in[10];
    const float* b3 = (const float*)d_in[11];
    float* out = (float*)d_out;

    void *p_X1, *p_X2, *p_HE, *p_Xs, *p_W1s, *p_W2s, *p_W3s;
    void *p_nd_cnt, *p_he_cnt, *p_sum, *p_sumsq;
    cudaGetSymbolAddress(&p_X1, g_X1);
    cudaGetSymbolAddress(&p_X2, g_X2);
    cudaGetSymbolAddress(&p_HE, g_HE);
    cudaGetSymbolAddress(&p_Xs, g_Xs);
    cudaGetSymbolAddress(&p_W1s, g_W1s);
    cudaGetSymbolAddress(&p_W2s, g_W2s);
    cudaGetSymbolAddress(&p_W3s, g_W3s);
    cudaGetSymbolAddress(&p_nd_cnt, g_nd_cnt);
    cudaGetSymbolAddress(&p_he_cnt, g_he_cnt);
    cudaGetSymbolAddress(&p_sum, g_sum);
    cudaGetSymbolAddress(&p_sumsq, g_sumsq);
    float* X1 = (float*)p_X1;
    float* X2 = (float*)p_X2;
    float* HE = (float*)p_HE;
    __half* Xs  = (__half*)p_Xs;
    __half* W1s = (__half*)p_W1s;
    __half* W2s = (__half*)p_W2s;
    __half* W3s = (__half*)p_W3s;
    float* bn_s = (float*)p_sum;
    float* bn_q = (float*)p_sumsq;

    const int GEMM1_SMEM = 98304;
    const int GEMM2_SMEM = 2048 + 2 * (32768 + 2 * 256 * 128);   // 198656 (NWN=4)
    const int GEMM3_SMEM = 2048 + 2 * (32768 + 2 * 128 * 128);   // 133120 (NWN=2)
    cudaFuncSetAttribute(gemm_f16_mma, cudaFuncAttributeMaxDynamicSharedMemorySize, GEMM1_SMEM);
    cudaFuncSetAttribute(gemm_bn_f16<4>, cudaFuncAttributeMaxDynamicSharedMemorySize, GEMM2_SMEM);
    cudaFuncSetAttribute(gemm_bn_f16<2>, cudaFuncAttributeMaxDynamicSharedMemorySize, GEMM3_SMEM);
    const int mtiles = (N_NODES + 127) / 128;

    // ---- weight splits ----
    k_split_W<<<(IN_CH * HID + 255) / 256, 256>>>(W1, W1s, IN_CH, HID);
    k_split_W<<<(HID * HID + 255) / 256, 256>>>(W2, W2s, HID, HID);
    k_split_W<<<(HID * OUT_CH + 255) / 256, 256>>>(W3, W3s, HID, OUT_CH);

    // ---- CSR build ----
    cudaMemsetAsync(p_nd_cnt, 0, N_NODES * sizeof(int));
    cudaMemsetAsync(p_he_cnt, 0, N_HE * sizeof(int));
    k_hist<<<(N_INC + 255) / 256, 256>>>(node_idx, he_idx);
    const int nb_nd = (N_NODES + 2047) / 2048;   // 49
    const int nb_he = (N_HE + 2047) / 2048;      // 15
    k_blk_sum2<<<nb_nd + nb_he, 256>>>(nb_nd);
    k_bsum_scan2<<<2, 1024>>>(nb_nd, nb_he);
    k_blk_scan2<<<nb_nd + nb_he, 256>>>(nb_nd);
    cudaMemsetAsync(p_nd_cnt, 0, N_NODES * sizeof(int));
    cudaMemsetAsync(p_he_cnt, 0, N_HE * sizeof(int));
    k_scatter<<<(N_INC + 255) / 256, 256>>>(node_idx, he_idx);

    const int bn_grid = (N_NODES + BN_ROWS_PER_BLOCK - 1) / BN_ROWS_PER_BLOCK;

    // ---- layer 1: aggregate first (A(xW)=(Ax)W), split fused into gather ----
    {
        k_he_gather<<<N_HE, IN_CH / 4>>>(x, HE, IN_CH / 4);
        k_node_gather_split<<<N_NODES, IN_CH / 4>>>(HE, Xs, IN_CH);
        dim3 grid(1, mtiles);
        gemm_f16_mma<<<grid, 512, GEMM1_SMEM>>>(Xs, W1s, X1, N_NODES, 2 * IN_CH, HID, b1, 1);
        cudaMemsetAsync(p_sum, 0, HID * sizeof(float));
        cudaMemsetAsync(p_sumsq, 0, HID * sizeof(float));
        k_bn_stats<<<bn_grid, HID>>>(X1);
    }
    // ---- layer 2: GEMM consumes X1 + BN1 params directly ----
    {
        dim3 grid(1, mtiles);
        gemm_bn_f16<4><<<grid, 512, GEMM2_SMEM>>>(X1, W2s, X2, N_NODES, HID, bn_s, bn_q, g1, be1);
        k_he_gather<<<N_HE, HID / 4>>>(X2, HE, HID / 4);
        k_node_gather<<<N_NODES, HID / 4>>>(HE, b2, X1, HID / 4);
        cudaMemsetAsync(p_sum, 0, HID * sizeof(float));
        cudaMemsetAsync(p_sumsq, 0, HID * sizeof(float));
        k_bn_stats<<<bn_grid, HID>>>(X1);
    }
    // ---- layer 3: GEMM consumes X1 + BN2 params directly ----
    {
        dim3 grid(1, mtiles);
        gemm_bn_f16<2><<<grid, 256, GEMM3_SMEM>>>(X1, W3s, X2, N_NODES, HID, bn_s, bn_q, g2, be2);
        k_he_gather<<<N_HE, OUT_CH / 4>>>(X2, HE, OUT_CH / 4);
        k_node_gather<<<N_NODES, OUT_CH / 4>>>(HE, b3, out, OUT_CH / 4);
    }
}